// round 1
// baseline (speedup 1.0000x reference)
#include <cuda_runtime.h>
#include <cstdint>
#include <math.h>

#define C 128
#define MAXN 100000
#define MAXE 50000

// ---------------- scratch (static device globals; no allocation) ----------------
__device__ float  g_eaccum[(size_t)MAXE * C];   // edge accumulator, then e_feat@W in-place
__device__ float  g_D[MAXN];
__device__ float  g_Dinv[MAXN];
__device__ float  g_Bdeg[MAXE];
__device__ float  g_Binv[MAXE];
__device__ double g_sum[C];
__device__ double g_sumsq[C];
__device__ float  g_scale[C];
__device__ float  g_shift[C];
__device__ int    g_is64;

// ---------------- helpers ----------------
__device__ __forceinline__ void red4(float* p, float4 v) {
    asm volatile("red.global.add.v4.f32 [%0], {%1,%2,%3,%4};"
                 :: "l"(p), "f"(v.x), "f"(v.y), "f"(v.z), "f"(v.w) : "memory");
}

__device__ __forceinline__ long ldidx(const void* base, long i) {
    if (g_is64) return (long)((const long long*)base)[i];
    return (long)((const int*)base)[i];
}

// ---------------- kernels ----------------

// Detect whether indices are int64 or int32: for int64 (values < 2^31) every
// odd 32-bit word is zero; for int32 random indices that's ~impossible for 64 entries.
__global__ void k_detect(const unsigned* p) {
    if (threadIdx.x == 0) {
        int is64 = 1;
        for (int i = 0; i < 64; i++) {
            if (p[2 * i + 1] != 0u) { is64 = 0; break; }
        }
        g_is64 = is64;
    }
}

// D[node] += w[edge]; Bdeg[edge] += 1
__global__ void k_degrees(const void* __restrict__ hidx, const float* __restrict__ w, int nnz) {
    long i = (long)blockIdx.x * blockDim.x + threadIdx.x;
    if (i >= nnz) return;
    long node = ldidx(hidx, i);
    long edge = ldidx(hidx, (long)nnz + i);
    atomicAdd(&g_D[node], w[edge]);
    atomicAdd(&g_Bdeg[edge], 1.0f);
}

__global__ void k_inv(int N, int E) {
    int i = blockIdx.x * blockDim.x + threadIdx.x;
    if (i < N) { float d = g_D[i];    g_Dinv[i] = d > 0.f ? 1.f / d : 0.f; }
    if (i < E) { float d = g_Bdeg[i]; g_Binv[i] = d > 0.f ? 1.f / d : 0.f; }
}

// Phase A: one warp per nnz entry; gather x[node] (32 float4), vector-red into eaccum[edge]
__global__ void k_scatter_x(const float* __restrict__ x, const void* __restrict__ hidx, int nnz) {
    long w = ((long)blockIdx.x << 3) + (threadIdx.x >> 5);
    if (w >= nnz) return;
    int lane = threadIdx.x & 31;
    long node = ldidx(hidx, w);
    long edge = ldidx(hidx, (long)nnz + w);
    float4 v = ((const float4*)x)[node * 32 + lane];
    red4(&g_eaccum[edge * C + lane * 4], v);
}

// GEMM (in place): eaccum[r][:] = (eaccum[r][:] * Binv[r]) @ W,  64-row blocks,
// 256 threads, 4x8 register micro-tile. W and (transposed) x-tile in dynamic smem.
#define GEMM_SMEM_BYTES ((128 * 132 + 128 * 68) * 4)
__global__ void k_gemm(const float* __restrict__ W, int E) {
    extern __shared__ float sm[];
    float (*ws)[132] = (float(*)[132])sm;                 // ws[k][c]
    float (*xs)[68]  = (float(*)[68])(sm + 128 * 132);    // xs[k][r] (transposed)
    int tid = threadIdx.x;

    // load W (128x128) into smem
    for (int i = tid; i < 128 * 32; i += 256) {
        int k = i >> 5, c4 = i & 31;
        float4 v = ((const float4*)W)[i];
        ws[k][c4 * 4 + 0] = v.x; ws[k][c4 * 4 + 1] = v.y;
        ws[k][c4 * 4 + 2] = v.z; ws[k][c4 * 4 + 3] = v.w;
    }
    // load 64-row x tile, scale by Binv, store transposed
    int r0 = blockIdx.x * 64;
    for (int i = tid; i < 64 * 32; i += 256) {
        int r = i >> 5, k4 = i & 31;
        int row = r0 + r;
        float4 v = make_float4(0.f, 0.f, 0.f, 0.f);
        float s = 0.f;
        if (row < E) {
            v = ((const float4*)g_eaccum)[(size_t)row * 32 + k4];
            s = g_Binv[row];
        }
        xs[k4 * 4 + 0][r] = v.x * s; xs[k4 * 4 + 1][r] = v.y * s;
        xs[k4 * 4 + 2][r] = v.z * s; xs[k4 * 4 + 3][r] = v.w * s;
    }
    __syncthreads();

    int tx = tid & 15, ty = tid >> 4;   // cols tx*8..+7, rows ty*4..+3
    float acc[4][8];
#pragma unroll
    for (int i = 0; i < 4; i++)
#pragma unroll
        for (int j = 0; j < 8; j++) acc[i][j] = 0.f;

#pragma unroll 4
    for (int k = 0; k < 128; k++) {
        float a4[4], b8[8];
        *(float4*)&a4[0] = *(const float4*)&xs[k][ty * 4];
        *(float4*)&b8[0] = *(const float4*)&ws[k][tx * 8];
        *(float4*)&b8[4] = *(const float4*)&ws[k][tx * 8 + 4];
#pragma unroll
        for (int i = 0; i < 4; i++)
#pragma unroll
            for (int j = 0; j < 8; j++) acc[i][j] += a4[i] * b8[j];
    }

#pragma unroll
    for (int i = 0; i < 4; i++) {
        int row = r0 + ty * 4 + i;
        if (row < E) {
            float4* dst = (float4*)&g_eaccum[(size_t)row * 128 + tx * 8];
            dst[0] = make_float4(acc[i][0], acc[i][1], acc[i][2], acc[i][3]);
            dst[1] = make_float4(acc[i][4], acc[i][5], acc[i][6], acc[i][7]);
        }
    }
}

// Phase B: one warp per nnz entry; gather e_featW[edge], vector-red into out[node]
__global__ void k_scatter_e(float* __restrict__ out, const void* __restrict__ hidx, int nnz) {
    long w = ((long)blockIdx.x << 3) + (threadIdx.x >> 5);
    if (w >= nnz) return;
    int lane = threadIdx.x & 31;
    long node = ldidx(hidx, w);
    long edge = ldidx(hidx, (long)nnz + w);
    float4 v = ((const float4*)g_eaccum)[edge * 32 + lane];
    red4(&out[node * C + lane * 4], v);
}

// out = out*Dinv + b  (in place), and accumulate per-channel sum / sumsq
__global__ void k_finalize(float* __restrict__ out, const float* __restrict__ b, int N) {
    int c = threadIdx.x & 127, y = threadIdx.x >> 7;  // blockDim 256
    float bc = b[c];
    float sum = 0.f, sq = 0.f;
    for (long r = (long)blockIdx.x * 2 + y; r < N; r += (long)gridDim.x * 2) {
        float v = out[r * 128 + c] * g_Dinv[r] + bc;
        out[r * 128 + c] = v;
        sum += v; sq += v * v;
    }
    __shared__ float s1[2][128], s2[2][128];
    s1[y][c] = sum; s2[y][c] = sq;
    __syncthreads();
    if (y == 0) {
        atomicAdd(&g_sum[c],   (double)(s1[0][c] + s1[1][c]));
        atomicAdd(&g_sumsq[c], (double)(s2[0][c] + s2[1][c]));
    }
}

__global__ void k_bnprep(const float* __restrict__ gamma, const float* __restrict__ beta, int N) {
    int c = threadIdx.x;
    double mean = g_sum[c] / (double)N;
    double var  = g_sumsq[c] / (double)N - mean * mean;
    float rstd = rsqrtf((float)var + 1e-5f);
    float sc = rstd * gamma[c];
    g_scale[c] = sc;
    g_shift[c] = beta[c] - (float)mean * sc;
}

__global__ void k_bnsilu(float* __restrict__ out, long n4) {
    long i = (long)blockIdx.x * blockDim.x + threadIdx.x;
    if (i >= n4) return;
    int c4 = (int)(i & 31);
    float4 v = ((float4*)out)[i];
    float r[4] = {v.x, v.y, v.z, v.w};
#pragma unroll
    for (int j = 0; j < 4; j++) {
        int c = c4 * 4 + j;
        float o = r[j] * g_scale[c] + g_shift[c];
        r[j] = o * (1.f / (1.f + expf(-o)));
    }
    ((float4*)out)[i] = make_float4(r[0], r[1], r[2], r[3]);
}

// ---------------- launcher ----------------
extern "C" void kernel_launch(void* const* d_in, const int* in_sizes, int n_in,
                              void* d_out, int out_size) {
    const float* x     = (const float*)d_in[0];
    const void*  hidx  = d_in[1];
    const float* hw    = (const float*)d_in[2];
    const float* W     = (const float*)d_in[3];
    const float* b     = (const float*)d_in[4];
    const float* gamma = (const float*)d_in[5];
    const float* beta  = (const float*)d_in[6];
    float* out = (float*)d_out;

    int N   = in_sizes[0] / C;
    int nnz = in_sizes[1] / 2;
    int E   = in_sizes[2];

    void *p_ea, *p_D, *p_B, *p_s, *p_sq;
    cudaGetSymbolAddress(&p_ea, g_eaccum);
    cudaGetSymbolAddress(&p_D,  g_D);
    cudaGetSymbolAddress(&p_B,  g_Bdeg);
    cudaGetSymbolAddress(&p_s,  g_sum);
    cudaGetSymbolAddress(&p_sq, g_sumsq);

    cudaMemsetAsync(p_ea, 0, (size_t)E * C * sizeof(float), 0);
    cudaMemsetAsync(p_D,  0, (size_t)N * sizeof(float), 0);
    cudaMemsetAsync(p_B,  0, (size_t)E * sizeof(float), 0);
    cudaMemsetAsync(p_s,  0, C * sizeof(double), 0);
    cudaMemsetAsync(p_sq, 0, C * sizeof(double), 0);
    cudaMemsetAsync(d_out, 0, (size_t)N * C * sizeof(float), 0);

    k_detect<<<1, 32>>>((const unsigned*)hidx);
    k_degrees<<<(nnz + 255) / 256, 256>>>(hidx, hw, nnz);
    int m = (N > E ? N : E);
    k_inv<<<(m + 255) / 256, 256>>>(N, E);

    k_scatter_x<<<(nnz + 7) / 8, 256>>>(x, hidx, nnz);

    cudaFuncSetAttribute(k_gemm, cudaFuncAttributeMaxDynamicSharedMemorySize, GEMM_SMEM_BYTES);
    k_gemm<<<(E + 63) / 64, 256, GEMM_SMEM_BYTES>>>(W, E);

    k_scatter_e<<<(nnz + 7) / 8, 256>>>(out, hidx, nnz);

    k_finalize<<<1024, 256>>>(out, b, N);
    k_bnprep<<<1, 128>>>(gamma, beta, N);

    long n4 = (long)N * 32;
    k_bnsilu<<<(int)((n4 + 255) / 256), 256>>>(out, n4);
}

// round 2
// speedup vs baseline: 1.5682x; 1.5682x over previous
#include <cuda_runtime.h>
#include <cstdint>
#include <math.h>

#define C 128
#define MAXN 100000
#define MAXE 50000
#define MAXNNZ 1600000

// ---------------- scratch (static device globals; no allocation) ----------------
__device__ float  g_eaccum[(size_t)MAXE * C];   // edge accumulator, then e_feat@W in-place
__device__ int    g_cntE[MAXE];
__device__ int    g_cntN[MAXN];
__device__ int    g_startE[MAXE];               // excl-scan, mutated into segment ENDs by build
__device__ int    g_startN[MAXN];
__device__ int    g_csrA[MAXNNZ];               // node ids grouped by edge
__device__ int    g_csrB[MAXNNZ];               // edge ids grouped by node
__device__ double g_sum[32 * C];                // slotted BN partials
__device__ double g_sumsq[32 * C];
__device__ float  g_scale[C];
__device__ float  g_shift[C];
__device__ int    g_is64;

// ---------------- helpers ----------------
__device__ __forceinline__ long ldidx(const void* base, long i) {
    if (g_is64) return (long)((const long long*)base)[i];
    return (long)((const int*)base)[i];
}

// ---------------- kernels ----------------

// Detect int64 vs int32 indices (values < 2^31 -> odd 32-bit words all zero for int64).
__global__ void k_detect(const unsigned* p) {
    if (threadIdx.x == 0) {
        int is64 = 1;
        for (int i = 0; i < 64; i++)
            if (p[2 * i + 1] != 0u) { is64 = 0; break; }
        g_is64 = is64;
    }
}

__global__ void k_count(const void* __restrict__ hidx, int nnz) {
    long i = (long)blockIdx.x * blockDim.x + threadIdx.x;
    if (i >= nnz) return;
    long node = ldidx(hidx, i);
    long edge = ldidx(hidx, (long)nnz + i);
    atomicAdd(&g_cntN[node], 1);
    atomicAdd(&g_cntE[edge], 1);
}

// Single-block exclusive scan (1024 threads, int4 tiles).
__global__ void k_scan(const int* __restrict__ cnt, int* __restrict__ start, int n) {
    __shared__ int warpsums[32];
    __shared__ int s_carry;
    int tid = threadIdx.x, lane = tid & 31, wid = tid >> 5;
    if (tid == 0) s_carry = 0;
    __syncthreads();
    const int TILE = 1024 * 4;
    for (int base = 0; base < n; base += TILE) {
        int i0 = base + tid * 4;
        int4 v = make_int4(0, 0, 0, 0);
        if (i0 + 3 < n) v = *(const int4*)(cnt + i0);
        else {
            if (i0 < n)     v.x = cnt[i0];
            if (i0 + 1 < n) v.y = cnt[i0 + 1];
            if (i0 + 2 < n) v.z = cnt[i0 + 2];
        }
        int t = v.x + v.y + v.z + v.w;
        int s = t;
        for (int o = 1; o < 32; o <<= 1) {
            int u = __shfl_up_sync(0xffffffffu, s, o);
            if (lane >= o) s += u;
        }
        if (lane == 31) warpsums[wid] = s;
        __syncthreads();
        if (wid == 0) {
            int ws = warpsums[lane];
            for (int o = 1; o < 32; o <<= 1) {
                int u = __shfl_up_sync(0xffffffffu, ws, o);
                if (lane >= o) ws += u;
            }
            warpsums[lane] = ws;
        }
        __syncthreads();
        int excl = s - t + (wid > 0 ? warpsums[wid - 1] : 0) + s_carry;
        int4 o4;
        o4.x = excl; o4.y = excl + v.x; o4.z = excl + v.x + v.y; o4.w = excl + v.x + v.y + v.z;
        if (i0 + 3 < n) *(int4*)(start + i0) = o4;
        else {
            if (i0 < n)     start[i0]     = o4.x;
            if (i0 + 1 < n) start[i0 + 1] = o4.y;
            if (i0 + 2 < n) start[i0 + 2] = o4.z;
        }
        __syncthreads();
        if (tid == 1023) s_carry = excl + t;
        __syncthreads();
    }
}

// Build both CSR permutations; atomicAdd on start doubles as cursor
// (after this kernel, g_startE[e] / g_startN[v] hold segment ENDs).
__global__ void k_build(const void* __restrict__ hidx, int nnz) {
    long i = (long)blockIdx.x * blockDim.x + threadIdx.x;
    if (i >= nnz) return;
    long node = ldidx(hidx, i);
    long edge = ldidx(hidx, (long)nnz + i);
    int pE = atomicAdd(&g_startE[edge], 1);
    g_csrA[pE] = (int)node;
    int pN = atomicAdd(&g_startN[node], 1);
    g_csrB[pN] = (int)edge;
}

// Phase A: warp per edge; gather incident node rows of x, apply B^-1, write eaccum.
__global__ void k_edge_gather(const float* __restrict__ x, int E) {
    int e = blockIdx.x * 8 + (threadIdx.x >> 5);
    if (e >= E) return;
    int lane = threadIdx.x & 31;
    int start = (e == 0) ? 0 : g_startE[e - 1];
    int end = g_startE[e];
    float4 acc = make_float4(0.f, 0.f, 0.f, 0.f);
    int i = start;
    for (; i + 32 <= end; i += 32) {
        int my = g_csrA[i + lane];
#pragma unroll 8
        for (int j = 0; j < 32; j++) {
            int nd = __shfl_sync(0xffffffffu, my, j);
            float4 v = ((const float4*)x)[(size_t)nd * 32 + lane];
            acc.x += v.x; acc.y += v.y; acc.z += v.z; acc.w += v.w;
        }
    }
    int rem = end - i;
    if (rem > 0) {
        int my = (lane < rem) ? g_csrA[i + lane] : 0;
#pragma unroll 4
        for (int j = 0; j < rem; j++) {
            int nd = __shfl_sync(0xffffffffu, my, j);
            float4 v = ((const float4*)x)[(size_t)nd * 32 + lane];
            acc.x += v.x; acc.y += v.y; acc.z += v.z; acc.w += v.w;
        }
    }
    float binv = (end > start) ? 1.f / (float)(end - start) : 0.f;
    acc.x *= binv; acc.y *= binv; acc.z *= binv; acc.w *= binv;
    ((float4*)g_eaccum)[(size_t)e * 32 + lane] = acc;
}

// GEMM in place: eaccum[r][:] = eaccum[r][:] @ W.  64-row blocks, 256 threads, 4x8 tile.
#define GEMM_SMEM_BYTES ((128 * 132 + 128 * 68) * 4)
__global__ void k_gemm(const float* __restrict__ W, int E) {
    extern __shared__ float sm[];
    float (*ws)[132] = (float(*)[132])sm;
    float (*xs)[68]  = (float(*)[68])(sm + 128 * 132);
    int tid = threadIdx.x;

    for (int i = tid; i < 128 * 32; i += 256) {
        int k = i >> 5, c4 = i & 31;
        float4 v = ((const float4*)W)[i];
        ws[k][c4 * 4 + 0] = v.x; ws[k][c4 * 4 + 1] = v.y;
        ws[k][c4 * 4 + 2] = v.z; ws[k][c4 * 4 + 3] = v.w;
    }
    int r0 = blockIdx.x * 64;
    for (int i = tid; i < 64 * 32; i += 256) {
        int r = i >> 5, k4 = i & 31;
        int row = r0 + r;
        float4 v = make_float4(0.f, 0.f, 0.f, 0.f);
        if (row < E) v = ((const float4*)g_eaccum)[(size_t)row * 32 + k4];
        xs[k4 * 4 + 0][r] = v.x; xs[k4 * 4 + 1][r] = v.y;
        xs[k4 * 4 + 2][r] = v.z; xs[k4 * 4 + 3][r] = v.w;
    }
    __syncthreads();

    int tx = tid & 15, ty = tid >> 4;
    float acc[4][8];
#pragma unroll
    for (int i = 0; i < 4; i++)
#pragma unroll
        for (int j = 0; j < 8; j++) acc[i][j] = 0.f;

#pragma unroll 4
    for (int k = 0; k < 128; k++) {
        float a4[4], b8[8];
        *(float4*)&a4[0] = *(const float4*)&xs[k][ty * 4];
        *(float4*)&b8[0] = *(const float4*)&ws[k][tx * 8];
        *(float4*)&b8[4] = *(const float4*)&ws[k][tx * 8 + 4];
#pragma unroll
        for (int i = 0; i < 4; i++)
#pragma unroll
            for (int j = 0; j < 8; j++) acc[i][j] += a4[i] * b8[j];
    }

#pragma unroll
    for (int i = 0; i < 4; i++) {
        int row = r0 + ty * 4 + i;
        if (row < E) {
            float4* dst = (float4*)&g_eaccum[(size_t)row * 128 + tx * 8];
            dst[0] = make_float4(acc[i][0], acc[i][1], acc[i][2], acc[i][3]);
            dst[1] = make_float4(acc[i][4], acc[i][5], acc[i][6], acc[i][7]);
        }
    }
}

// Phase B: warp per node (grid-stride). Gather e_featW rows, compute D^-1 from w
// on the fly, add bias, write out, accumulate BN partial sums into 32 slots.
__global__ void k_node_gather(const float* __restrict__ hw, const float* __restrict__ b,
                              float* __restrict__ out, int N) {
    int lane = threadIdx.x & 31;
    int gwarp = (int)((blockIdx.x * blockDim.x + threadIdx.x) >> 5);
    int nw = (int)((gridDim.x * blockDim.x) >> 5);
    float4 bc = ((const float4*)b)[lane];
    float4 s1 = make_float4(0.f, 0.f, 0.f, 0.f);
    float4 s2 = make_float4(0.f, 0.f, 0.f, 0.f);

    for (int v = gwarp; v < N; v += nw) {
        int start = (v == 0) ? 0 : g_startN[v - 1];
        int end = g_startN[v];
        float4 acc = make_float4(0.f, 0.f, 0.f, 0.f);
        float wsum = 0.f;
        int i = start;
        for (; i + 32 <= end; i += 32) {
            int my = g_csrB[i + lane];
#pragma unroll 8
            for (int j = 0; j < 32; j++) {
                int e = __shfl_sync(0xffffffffu, my, j);
                float4 t = ((const float4*)g_eaccum)[(size_t)e * 32 + lane];
                acc.x += t.x; acc.y += t.y; acc.z += t.z; acc.w += t.w;
                wsum += __ldg(&hw[e]);
            }
        }
        int rem = end - i;
        if (rem > 0) {
            int my = (lane < rem) ? g_csrB[i + lane] : 0;
#pragma unroll 4
            for (int j = 0; j < rem; j++) {
                int e = __shfl_sync(0xffffffffu, my, j);
                float4 t = ((const float4*)g_eaccum)[(size_t)e * 32 + lane];
                acc.x += t.x; acc.y += t.y; acc.z += t.z; acc.w += t.w;
                wsum += __ldg(&hw[e]);
            }
        }
        float dinv = wsum > 0.f ? 1.f / wsum : 0.f;
        float4 val;
        val.x = acc.x * dinv + bc.x; val.y = acc.y * dinv + bc.y;
        val.z = acc.z * dinv + bc.z; val.w = acc.w * dinv + bc.w;
        ((float4*)out)[(size_t)v * 32 + lane] = val;
        s1.x += val.x; s1.y += val.y; s1.z += val.z; s1.w += val.w;
        s2.x += val.x * val.x; s2.y += val.y * val.y;
        s2.z += val.z * val.z; s2.w += val.w * val.w;
    }

    __shared__ float sh1[128], sh2[128];
    int tid = threadIdx.x;
    if (tid < 128) { sh1[tid] = 0.f; sh2[tid] = 0.f; }
    __syncthreads();
    int c0 = lane * 4;
    atomicAdd(&sh1[c0 + 0], s1.x); atomicAdd(&sh1[c0 + 1], s1.y);
    atomicAdd(&sh1[c0 + 2], s1.z); atomicAdd(&sh1[c0 + 3], s1.w);
    atomicAdd(&sh2[c0 + 0], s2.x); atomicAdd(&sh2[c0 + 1], s2.y);
    atomicAdd(&sh2[c0 + 2], s2.z); atomicAdd(&sh2[c0 + 3], s2.w);
    __syncthreads();
    if (tid < 128) {
        int slot = blockIdx.x & 31;
        atomicAdd(&g_sum[slot * 128 + tid],   (double)sh1[tid]);
        atomicAdd(&g_sumsq[slot * 128 + tid], (double)sh2[tid]);
    }
}

__global__ void k_bnprep(const float* __restrict__ gamma, const float* __restrict__ beta, int N) {
    int c = threadIdx.x;
    double s = 0.0, q = 0.0;
    for (int k = 0; k < 32; k++) { s += g_sum[k * 128 + c]; q += g_sumsq[k * 128 + c]; }
    double mean = s / (double)N;
    double var  = q / (double)N - mean * mean;
    float rstd = rsqrtf((float)var + 1e-5f);
    float sc = rstd * gamma[c];
    g_scale[c] = sc;
    g_shift[c] = beta[c] - (float)mean * sc;
}

__global__ void k_bnsilu(float* __restrict__ out, long n4) {
    long i = (long)blockIdx.x * blockDim.x + threadIdx.x;
    if (i >= n4) return;
    int c4 = (int)(i & 31);
    float4 v = ((float4*)out)[i];
    float r[4] = {v.x, v.y, v.z, v.w};
#pragma unroll
    for (int j = 0; j < 4; j++) {
        int c = c4 * 4 + j;
        float o = r[j] * g_scale[c] + g_shift[c];
        r[j] = o * (1.f / (1.f + __expf(-o)));
    }
    ((float4*)out)[i] = make_float4(r[0], r[1], r[2], r[3]);
}

// ---------------- launcher ----------------
extern "C" void kernel_launch(void* const* d_in, const int* in_sizes, int n_in,
                              void* d_out, int out_size) {
    const float* x     = (const float*)d_in[0];
    const void*  hidx  = d_in[1];
    const float* hw    = (const float*)d_in[2];
    const float* W     = (const float*)d_in[3];
    const float* b     = (const float*)d_in[4];
    const float* gamma = (const float*)d_in[5];
    const float* beta  = (const float*)d_in[6];
    float* out = (float*)d_out;

    int N   = in_sizes[0] / C;
    int nnz = in_sizes[1] / 2;
    int E   = in_sizes[2];

    void *p_cE, *p_cN, *p_s, *p_sq, *p_stE, *p_stN;
    cudaGetSymbolAddress(&p_cE,  g_cntE);
    cudaGetSymbolAddress(&p_cN,  g_cntN);
    cudaGetSymbolAddress(&p_s,   g_sum);
    cudaGetSymbolAddress(&p_sq,  g_sumsq);
    cudaGetSymbolAddress(&p_stE, g_startE);
    cudaGetSymbolAddress(&p_stN, g_startN);

    cudaMemsetAsync(p_cE, 0, (size_t)E * sizeof(int), 0);
    cudaMemsetAsync(p_cN, 0, (size_t)N * sizeof(int), 0);
    cudaMemsetAsync(p_s,  0, 32 * C * sizeof(double), 0);
    cudaMemsetAsync(p_sq, 0, 32 * C * sizeof(double), 0);

    k_detect<<<1, 32>>>((const unsigned*)hidx);
    k_count<<<(nnz + 255) / 256, 256>>>(hidx, nnz);
    k_scan<<<1, 1024>>>((const int*)p_cE, (int*)p_stE, E);
    k_scan<<<1, 1024>>>((const int*)p_cN, (int*)p_stN, N);
    k_build<<<(nnz + 255) / 256, 256>>>(hidx, nnz);

    k_edge_gather<<<(E + 7) / 8, 256>>>(x, E);

    cudaFuncSetAttribute(k_gemm, cudaFuncAttributeMaxDynamicSharedMemorySize, GEMM_SMEM_BYTES);
    k_gemm<<<(E + 63) / 64, 256, GEMM_SMEM_BYTES>>>(W, E);

    k_node_gather<<<2048, 256>>>(hw, b, out, N);

    k_bnprep<<<1, 128>>>(gamma, beta, N);

    long n4 = (long)N * 32;
    k_bnsilu<<<(int)((n4 + 255) / 256), 256>>>(out, n4);
}

// round 3
// speedup vs baseline: 1.6880x; 1.0764x over previous
#include <cuda_runtime.h>
#include <cstdint>
#include <math.h>

#define C 128
#define MAXN 100000
#define MAXE 50000
#define MAXNNZ 1600000
#define SCAN_TILE 4096

// ---------------- scratch (static device globals; no allocation) ----------------
__device__ float  g_eaccum[(size_t)MAXE * C];   // edge accumulator, then e_feat@W in-place
__device__ int    g_cntE[MAXE];
__device__ int    g_cntN[MAXN];
__device__ int    g_startE[MAXE];               // excl-scan, mutated into segment ENDs by build
__device__ int    g_startN[MAXN];
__device__ int    g_csrA[MAXNNZ];               // node ids grouped by edge
__device__ int    g_csrB[MAXNNZ];               // edge ids grouped by node
__device__ int    g_bsum[128];                  // scan block sums
__device__ double g_sum[32 * C];                // slotted BN partials
__device__ double g_sumsq[32 * C];
__device__ float  g_scale[C];
__device__ float  g_shift[C];
__device__ int    g_is64;

// ---------------- helpers ----------------
__device__ __forceinline__ long ldidx(const void* base, long i) {
    if (g_is64) return (long)((const long long*)base)[i];
    return (long)((const int*)base)[i];
}

// ---------------- kernels ----------------

// Detect int64 vs int32 indices (values < 2^31 -> odd 32-bit words all zero for int64).
__global__ void k_detect(const unsigned* p) {
    if (threadIdx.x == 0) {
        int is64 = 1;
        for (int i = 0; i < 64; i++)
            if (p[2 * i + 1] != 0u) { is64 = 0; break; }
        g_is64 = is64;
    }
}

__global__ void k_count(const void* __restrict__ hidx, int nnz) {
    long i = (long)blockIdx.x * blockDim.x + threadIdx.x;
    if (i >= nnz) return;
    long node = ldidx(hidx, i);
    long edge = ldidx(hidx, (long)nnz + i);
    atomicAdd(&g_cntN[node], 1);
    atomicAdd(&g_cntE[edge], 1);
}

// ---- fused multi-block exclusive scan over BOTH count arrays ----
// pass 1: block-local exclusive scan of one 4096-elem tile + record block total
__global__ void k_scan1(int E, int N, int nbE) {
    __shared__ int warpsums[32];
    int bi = blockIdx.x;
    const int* src; int* dst; int n; int tile;
    if (bi < nbE) { src = g_cntE; dst = g_startE; n = E; tile = bi; }
    else          { src = g_cntN; dst = g_startN; n = N; tile = bi - nbE; }
    int tid = threadIdx.x, lane = tid & 31, wid = tid >> 5;
    int i0 = tile * SCAN_TILE + tid * 4;

    int4 v = make_int4(0, 0, 0, 0);
    if (i0 + 3 < n) v = *(const int4*)(src + i0);
    else {
        if (i0 < n)     v.x = src[i0];
        if (i0 + 1 < n) v.y = src[i0 + 1];
        if (i0 + 2 < n) v.z = src[i0 + 2];
    }
    int t = v.x + v.y + v.z + v.w;
    int s = t;
    for (int o = 1; o < 32; o <<= 1) {
        int u = __shfl_up_sync(0xffffffffu, s, o);
        if (lane >= o) s += u;
    }
    if (lane == 31) warpsums[wid] = s;
    __syncthreads();
    if (wid == 0) {
        int ws = warpsums[lane];
        for (int o = 1; o < 32; o <<= 1) {
            int u = __shfl_up_sync(0xffffffffu, ws, o);
            if (lane >= o) ws += u;
        }
        warpsums[lane] = ws;
        if (lane == 31) g_bsum[bi] = ws;   // block total
    }
    __syncthreads();
    int excl = s - t + (wid > 0 ? warpsums[wid - 1] : 0);
    int4 o4;
    o4.x = excl; o4.y = excl + v.x; o4.z = excl + v.x + v.y; o4.w = excl + v.x + v.y + v.z;
    if (i0 + 3 < n) *(int4*)(dst + i0) = o4;
    else {
        if (i0 < n)     dst[i0]     = o4.x;
        if (i0 + 1 < n) dst[i0 + 1] = o4.y;
        if (i0 + 2 < n) dst[i0 + 2] = o4.z;
    }
}

// pass 2: exclusive-scan the block sums, independently for the E and N ranges
__global__ void k_scan2(int nbE, int nbTot) {
    int tid = threadIdx.x;
    if (tid == 0) {
        int run = 0;
        for (int i = 0; i < nbE; i++) { int t = g_bsum[i]; g_bsum[i] = run; run += t; }
    } else if (tid == 1) {
        int run = 0;
        for (int i = nbE; i < nbTot; i++) { int t = g_bsum[i]; g_bsum[i] = run; run += t; }
    }
}

// pass 3: add scanned block offsets
__global__ void k_scan3(int E, int N, int nbE) {
    int bi = blockIdx.x;
    int* dst; int n; int tile;
    if (bi < nbE) { dst = g_startE; n = E; tile = bi; }
    else          { dst = g_startN; n = N; tile = bi - nbE; }
    int off = g_bsum[bi];
    if (off == 0) return;
    int i0 = tile * SCAN_TILE + threadIdx.x * 4;
    if (i0 + 3 < n) {
        int4 v = *(const int4*)(dst + i0);
        v.x += off; v.y += off; v.z += off; v.w += off;
        *(int4*)(dst + i0) = v;
    } else {
        if (i0 < n)     dst[i0]     += off;
        if (i0 + 1 < n) dst[i0 + 1] += off;
        if (i0 + 2 < n) dst[i0 + 2] += off;
    }
}

// Build both CSR permutations; atomicAdd on start doubles as cursor
// (after this kernel, g_startE[e] / g_startN[v] hold segment ENDs).
__global__ void k_build(const void* __restrict__ hidx, int nnz) {
    long i = (long)blockIdx.x * blockDim.x + threadIdx.x;
    if (i >= nnz) return;
    long node = ldidx(hidx, i);
    long edge = ldidx(hidx, (long)nnz + i);
    int pE = atomicAdd(&g_startE[edge], 1);
    g_csrA[pE] = (int)node;
    int pN = atomicAdd(&g_startN[node], 1);
    g_csrB[pN] = (int)edge;
}

// Phase A: warp per edge; gather incident node rows of x, apply B^-1, write eaccum.
__global__ void k_edge_gather(const float* __restrict__ x, int E) {
    int e = blockIdx.x * 8 + (threadIdx.x >> 5);
    if (e >= E) return;
    int lane = threadIdx.x & 31;
    int start = (e == 0) ? 0 : g_startE[e - 1];
    int end = g_startE[e];
    float4 acc = make_float4(0.f, 0.f, 0.f, 0.f);
    int i = start;
    for (; i + 32 <= end; i += 32) {
        int my = g_csrA[i + lane];
#pragma unroll 8
        for (int j = 0; j < 32; j++) {
            int nd = __shfl_sync(0xffffffffu, my, j);
            float4 v = ((const float4*)x)[(size_t)nd * 32 + lane];
            acc.x += v.x; acc.y += v.y; acc.z += v.z; acc.w += v.w;
        }
    }
    int rem = end - i;
    if (rem > 0) {
        int my = (lane < rem) ? g_csrA[i + lane] : 0;
#pragma unroll 4
        for (int j = 0; j < rem; j++) {
            int nd = __shfl_sync(0xffffffffu, my, j);
            float4 v = ((const float4*)x)[(size_t)nd * 32 + lane];
            acc.x += v.x; acc.y += v.y; acc.z += v.z; acc.w += v.w;
        }
    }
    float binv = (end > start) ? 1.f / (float)(end - start) : 0.f;
    acc.x *= binv; acc.y *= binv; acc.z *= binv; acc.w *= binv;
    ((float4*)g_eaccum)[(size_t)e * 32 + lane] = acc;
}

// GEMM in place: eaccum[r][:] = eaccum[r][:] @ W.  64-row blocks, 256 threads, 4x8 tile.
#define GEMM_SMEM_BYTES ((128 * 132 + 128 * 68) * 4)
__global__ void k_gemm(const float* __restrict__ W, int E) {
    extern __shared__ float sm[];
    float (*ws)[132] = (float(*)[132])sm;
    float (*xs)[68]  = (float(*)[68])(sm + 128 * 132);
    int tid = threadIdx.x;

    for (int i = tid; i < 128 * 32; i += 256) {
        int k = i >> 5, c4 = i & 31;
        float4 v = ((const float4*)W)[i];
        ws[k][c4 * 4 + 0] = v.x; ws[k][c4 * 4 + 1] = v.y;
        ws[k][c4 * 4 + 2] = v.z; ws[k][c4 * 4 + 3] = v.w;
    }
    int r0 = blockIdx.x * 64;
    for (int i = tid; i < 64 * 32; i += 256) {
        int r = i >> 5, k4 = i & 31;
        int row = r0 + r;
        float4 v = make_float4(0.f, 0.f, 0.f, 0.f);
        if (row < E) v = ((const float4*)g_eaccum)[(size_t)row * 32 + k4];
        xs[k4 * 4 + 0][r] = v.x; xs[k4 * 4 + 1][r] = v.y;
        xs[k4 * 4 + 2][r] = v.z; xs[k4 * 4 + 3][r] = v.w;
    }
    __syncthreads();

    int tx = tid & 15, ty = tid >> 4;
    float acc[4][8];
#pragma unroll
    for (int i = 0; i < 4; i++)
#pragma unroll
        for (int j = 0; j < 8; j++) acc[i][j] = 0.f;

#pragma unroll 4
    for (int k = 0; k < 128; k++) {
        float a4[4], b8[8];
        *(float4*)&a4[0] = *(const float4*)&xs[k][ty * 4];
        *(float4*)&b8[0] = *(const float4*)&ws[k][tx * 8];
        *(float4*)&b8[4] = *(const float4*)&ws[k][tx * 8 + 4];
#pragma unroll
        for (int i = 0; i < 4; i++)
#pragma unroll
            for (int j = 0; j < 8; j++) acc[i][j] += a4[i] * b8[j];
    }

#pragma unroll
    for (int i = 0; i < 4; i++) {
        int row = r0 + ty * 4 + i;
        if (row < E) {
            float4* dst = (float4*)&g_eaccum[(size_t)row * 128 + tx * 8];
            dst[0] = make_float4(acc[i][0], acc[i][1], acc[i][2], acc[i][3]);
            dst[1] = make_float4(acc[i][4], acc[i][5], acc[i][6], acc[i][7]);
        }
    }
}

// Phase B: warp per node (grid-stride). Gather e_featW rows, compute D^-1 from w
// on the fly, add bias, write out, accumulate BN partial sums into 32 slots.
__global__ void k_node_gather(const float* __restrict__ hw, const float* __restrict__ b,
                              float* __restrict__ out, int N) {
    int lane = threadIdx.x & 31;
    int gwarp = (int)((blockIdx.x * blockDim.x + threadIdx.x) >> 5);
    int nw = (int)((gridDim.x * blockDim.x) >> 5);
    float4 bc = ((const float4*)b)[lane];
    float4 s1 = make_float4(0.f, 0.f, 0.f, 0.f);
    float4 s2 = make_float4(0.f, 0.f, 0.f, 0.f);

    for (int v = gwarp; v < N; v += nw) {
        int start = (v == 0) ? 0 : g_startN[v - 1];
        int end = g_startN[v];
        float4 acc = make_float4(0.f, 0.f, 0.f, 0.f);
        float wsum = 0.f;
        int i = start;
        for (; i + 32 <= end; i += 32) {
            int my = g_csrB[i + lane];
#pragma unroll 8
            for (int j = 0; j < 32; j++) {
                int e = __shfl_sync(0xffffffffu, my, j);
                float4 t = ((const float4*)g_eaccum)[(size_t)e * 32 + lane];
                acc.x += t.x; acc.y += t.y; acc.z += t.z; acc.w += t.w;
                wsum += __ldg(&hw[e]);
            }
        }
        int rem = end - i;
        if (rem > 0) {
            int my = (lane < rem) ? g_csrB[i + lane] : 0;
#pragma unroll 4
            for (int j = 0; j < rem; j++) {
                int e = __shfl_sync(0xffffffffu, my, j);
                float4 t = ((const float4*)g_eaccum)[(size_t)e * 32 + lane];
                acc.x += t.x; acc.y += t.y; acc.z += t.z; acc.w += t.w;
                wsum += __ldg(&hw[e]);
            }
        }
        float dinv = wsum > 0.f ? 1.f / wsum : 0.f;
        float4 val;
        val.x = acc.x * dinv + bc.x; val.y = acc.y * dinv + bc.y;
        val.z = acc.z * dinv + bc.z; val.w = acc.w * dinv + bc.w;
        ((float4*)out)[(size_t)v * 32 + lane] = val;
        s1.x += val.x; s1.y += val.y; s1.z += val.z; s1.w += val.w;
        s2.x += val.x * val.x; s2.y += val.y * val.y;
        s2.z += val.z * val.z; s2.w += val.w * val.w;
    }

    __shared__ float sh1[128], sh2[128];
    int tid = threadIdx.x;
    if (tid < 128) { sh1[tid] = 0.f; sh2[tid] = 0.f; }
    __syncthreads();
    int c0 = lane * 4;
    atomicAdd(&sh1[c0 + 0], s1.x); atomicAdd(&sh1[c0 + 1], s1.y);
    atomicAdd(&sh1[c0 + 2], s1.z); atomicAdd(&sh1[c0 + 3], s1.w);
    atomicAdd(&sh2[c0 + 0], s2.x); atomicAdd(&sh2[c0 + 1], s2.y);
    atomicAdd(&sh2[c0 + 2], s2.z); atomicAdd(&sh2[c0 + 3], s2.w);
    __syncthreads();
    if (tid < 128) {
        int slot = blockIdx.x & 31;
        atomicAdd(&g_sum[slot * 128 + tid],   (double)sh1[tid]);
        atomicAdd(&g_sumsq[slot * 128 + tid], (double)sh2[tid]);
    }
}

__global__ void k_bnprep(const float* __restrict__ gamma, const float* __restrict__ beta, int N) {
    int c = threadIdx.x;
    double s = 0.0, q = 0.0;
    for (int k = 0; k < 32; k++) { s += g_sum[k * 128 + c]; q += g_sumsq[k * 128 + c]; }
    double mean = s / (double)N;
    double var  = q / (double)N - mean * mean;
    float rstd = rsqrtf((float)var + 1e-5f);
    float sc = rstd * gamma[c];
    g_scale[c] = sc;
    g_shift[c] = beta[c] - (float)mean * sc;
}

__global__ void k_bnsilu(float* __restrict__ out, long n4) {
    long i = (long)blockIdx.x * blockDim.x + threadIdx.x;
    if (i >= n4) return;
    int c4 = (int)(i & 31);
    float4 v = ((float4*)out)[i];
    float r[4] = {v.x, v.y, v.z, v.w};
#pragma unroll
    for (int j = 0; j < 4; j++) {
        int c = c4 * 4 + j;
        float o = r[j] * g_scale[c] + g_shift[c];
        r[j] = o * (1.f / (1.f + __expf(-o)));
    }
    ((float4*)out)[i] = make_float4(r[0], r[1], r[2], r[3]);
}

// ---------------- launcher ----------------
extern "C" void kernel_launch(void* const* d_in, const int* in_sizes, int n_in,
                              void* d_out, int out_size) {
    const float* x     = (const float*)d_in[0];
    const void*  hidx  = d_in[1];
    const float* hw    = (const float*)d_in[2];
    const float* W     = (const float*)d_in[3];
    const float* b     = (const float*)d_in[4];
    const float* gamma = (const float*)d_in[5];
    const float* beta  = (const float*)d_in[6];
    float* out = (float*)d_out;

    int N   = in_sizes[0] / C;
    int nnz = in_sizes[1] / 2;
    int E   = in_sizes[2];

    void *p_cE, *p_cN, *p_s, *p_sq;
    cudaGetSymbolAddress(&p_cE,  g_cntE);
    cudaGetSymbolAddress(&p_cN,  g_cntN);
    cudaGetSymbolAddress(&p_s,   g_sum);
    cudaGetSymbolAddress(&p_sq,  g_sumsq);

    cudaMemsetAsync(p_cE, 0, (size_t)E * sizeof(int), 0);
    cudaMemsetAsync(p_cN, 0, (size_t)N * sizeof(int), 0);
    cudaMemsetAsync(p_s,  0, 32 * C * sizeof(double), 0);
    cudaMemsetAsync(p_sq, 0, 32 * C * sizeof(double), 0);

    k_detect<<<1, 32>>>((const unsigned*)hidx);
    k_count<<<(nnz + 255) / 256, 256>>>(hidx, nnz);

    int nbE = (E + SCAN_TILE - 1) / SCAN_TILE;
    int nbN = (N + SCAN_TILE - 1) / SCAN_TILE;
    int nbTot = nbE + nbN;
    k_scan1<<<nbTot, 1024>>>(E, N, nbE);
    k_scan2<<<1, 32>>>(nbE, nbTot);
    k_scan3<<<nbTot, 1024>>>(E, N, nbE);

    k_build<<<(nnz + 255) / 256, 256>>>(hidx, nnz);

    k_edge_gather<<<(E + 7) / 8, 256>>>(x, E);

    cudaFuncSetAttribute(k_gemm, cudaFuncAttributeMaxDynamicSharedMemorySize, GEMM_SMEM_BYTES);
    k_gemm<<<(E + 63) / 64, 256, GEMM_SMEM_BYTES>>>(W, E);

    k_node_gather<<<2048, 256>>>(hw, b, out, N);

    k_bnprep<<<1, 128>>>(gamma, beta, N);

    long n4 = (long)N * 32;
    k_bnsilu<<<(int)((n4 + 255) / 256), 256>>>(out, n4);
}

// round 4
// speedup vs baseline: 1.8027x; 1.0679x over previous
#include <cuda_runtime.h>
#include <cstdint>
#include <math.h>

#define C 128
#define MAXN 100000
#define MAXE 50000
#define MAXNNZ 1600000
#define SCAN_TILE 4096

// ---------------- scratch (static device globals; no allocation) ----------------
__device__ float  g_eaccum[(size_t)MAXE * C];   // edge accumulator, then e_feat@W in-place
__device__ int    g_cntE[MAXE];
__device__ int    g_cntN[MAXN];
__device__ int    g_startE[MAXE];               // excl-scan, mutated into segment ENDs by build
__device__ int    g_startN[MAXN];
__device__ int    g_csrA[MAXNNZ];               // node ids grouped by edge
__device__ int    g_csrB[MAXNNZ];               // edge ids grouped by node
__device__ int    g_bsumE[64];
__device__ int    g_bsumN[64];
__device__ double g_sum[32 * C];                // slotted BN partials
__device__ double g_sumsq[32 * C];
__device__ float  g_scale[C];
__device__ float  g_shift[C];
__device__ int    g_is64;

// ---------------- helpers ----------------
__device__ __forceinline__ long ldidx(const void* base, long i) {
    if (g_is64) return (long)((const long long*)base)[i];
    return (long)((const int*)base)[i];
}

__device__ __forceinline__ void fma2(unsigned long long& d, unsigned long long a, unsigned long long b) {
    asm("fma.rn.f32x2 %0, %1, %2, %0;" : "+l"(d) : "l"(a), "l"(b));
}
__device__ __forceinline__ unsigned long long pack2(float lo, float hi) {
    unsigned long long r;
    asm("mov.b64 %0, {%1, %2};" : "=l"(r) : "f"(lo), "f"(hi));
    return r;
}

// ---------------- kernels ----------------

// Detect int64 vs int32 indices (values < 2^31 -> odd 32-bit words all zero for int64).
__global__ void k_detect(const unsigned* p) {
    if (threadIdx.x == 0) {
        int is64 = 1;
        for (int i = 0; i < 64; i++)
            if (p[2 * i + 1] != 0u) { is64 = 0; break; }
        g_is64 = is64;
    }
}

// count halves (each reads only its own index row)
__global__ void k_countE(const void* __restrict__ hidx, int nnz) {
    long i = (long)blockIdx.x * blockDim.x + threadIdx.x;
    if (i >= nnz) return;
    long edge = ldidx(hidx, (long)nnz + i);
    atomicAdd(&g_cntE[edge], 1);
}
__global__ void k_countN(const void* __restrict__ hidx, int nnz) {
    long i = (long)blockIdx.x * blockDim.x + threadIdx.x;
    if (i >= nnz) return;
    long node = ldidx(hidx, i);
    atomicAdd(&g_cntN[node], 1);
}

// pass 1: block-local exclusive scan of one 4096-elem tile + record block total
__global__ void k_scan_local(const int* __restrict__ src, int* __restrict__ dst,
                             int* __restrict__ bsum, int n) {
    __shared__ int warpsums[32];
    int tid = threadIdx.x, lane = tid & 31, wid = tid >> 5;
    int i0 = blockIdx.x * SCAN_TILE + tid * 4;

    int4 v = make_int4(0, 0, 0, 0);
    if (i0 + 3 < n) v = *(const int4*)(src + i0);
    else {
        if (i0 < n)     v.x = src[i0];
        if (i0 + 1 < n) v.y = src[i0 + 1];
        if (i0 + 2 < n) v.z = src[i0 + 2];
    }
    int t = v.x + v.y + v.z + v.w;
    int s = t;
    for (int o = 1; o < 32; o <<= 1) {
        int u = __shfl_up_sync(0xffffffffu, s, o);
        if (lane >= o) s += u;
    }
    if (lane == 31) warpsums[wid] = s;
    __syncthreads();
    if (wid == 0) {
        int ws = warpsums[lane];
        for (int o = 1; o < 32; o <<= 1) {
            int u = __shfl_up_sync(0xffffffffu, ws, o);
            if (lane >= o) ws += u;
        }
        warpsums[lane] = ws;
        if (lane == 31) bsum[blockIdx.x] = ws;
    }
    __syncthreads();
    int excl = s - t + (wid > 0 ? warpsums[wid - 1] : 0);
    int4 o4;
    o4.x = excl; o4.y = excl + v.x; o4.z = excl + v.x + v.y; o4.w = excl + v.x + v.y + v.z;
    if (i0 + 3 < n) *(int4*)(dst + i0) = o4;
    else {
        if (i0 < n)     dst[i0]     = o4.x;
        if (i0 + 1 < n) dst[i0 + 1] = o4.y;
        if (i0 + 2 < n) dst[i0 + 2] = o4.z;
    }
}

// fused pass 2+3: each block serially sums bsum[0..bi) (<=64 ints) and adds.
__global__ void k_scan_add(int* __restrict__ dst, const int* __restrict__ bsum, int n) {
    __shared__ int s_off;
    int bi = blockIdx.x;
    if (threadIdx.x == 0) {
        int run = 0;
        for (int k = 0; k < bi; k++) run += bsum[k];
        s_off = run;
    }
    __syncthreads();
    int off = s_off;
    if (off == 0) return;
    int i0 = bi * SCAN_TILE + threadIdx.x * 4;
    if (i0 + 3 < n) {
        int4 v = *(const int4*)(dst + i0);
        v.x += off; v.y += off; v.z += off; v.w += off;
        *(int4*)(dst + i0) = v;
    } else {
        if (i0 < n)     dst[i0]     += off;
        if (i0 + 1 < n) dst[i0 + 1] += off;
        if (i0 + 2 < n) dst[i0 + 2] += off;
    }
}

// Build CSR halves; atomicAdd on start doubles as cursor (start -> segment ENDs).
__global__ void k_buildE(const void* __restrict__ hidx, int nnz) {
    long i = (long)blockIdx.x * blockDim.x + threadIdx.x;
    if (i >= nnz) return;
    long node = ldidx(hidx, i);
    long edge = ldidx(hidx, (long)nnz + i);
    int pE = atomicAdd(&g_startE[edge], 1);
    g_csrA[pE] = (int)node;
}
__global__ void k_buildN(const void* __restrict__ hidx, int nnz) {
    long i = (long)blockIdx.x * blockDim.x + threadIdx.x;
    if (i >= nnz) return;
    long node = ldidx(hidx, i);
    long edge = ldidx(hidx, (long)nnz + i);
    int pN = atomicAdd(&g_startN[node], 1);
    g_csrB[pN] = (int)edge;
}

// Phase A: warp per edge; gather incident node rows of x, apply B^-1, write eaccum.
__global__ void k_edge_gather(const float* __restrict__ x, int E) {
    int e = blockIdx.x * 8 + (threadIdx.x >> 5);
    if (e >= E) return;
    int lane = threadIdx.x & 31;
    int start = (e == 0) ? 0 : g_startE[e - 1];
    int end = g_startE[e];
    float4 acc = make_float4(0.f, 0.f, 0.f, 0.f);
    int i = start;
    for (; i + 32 <= end; i += 32) {
        int my = g_csrA[i + lane];
#pragma unroll 8
        for (int j = 0; j < 32; j++) {
            int nd = __shfl_sync(0xffffffffu, my, j);
            float4 v = ((const float4*)x)[(size_t)nd * 32 + lane];
            acc.x += v.x; acc.y += v.y; acc.z += v.z; acc.w += v.w;
        }
    }
    int rem = end - i;
    if (rem > 0) {
        int my = (lane < rem) ? g_csrA[i + lane] : 0;
#pragma unroll 4
        for (int j = 0; j < rem; j++) {
            int nd = __shfl_sync(0xffffffffu, my, j);
            float4 v = ((const float4*)x)[(size_t)nd * 32 + lane];
            acc.x += v.x; acc.y += v.y; acc.z += v.z; acc.w += v.w;
        }
    }
    float binv = (end > start) ? 1.f / (float)(end - start) : 0.f;
    acc.x *= binv; acc.y *= binv; acc.z *= binv; acc.w *= binv;
    ((float4*)g_eaccum)[(size_t)e * 32 + lane] = acc;
}

// GEMM in place: eaccum[r][:] = eaccum[r][:] @ W.  64-row blocks, 256 threads,
// 4x8 register tile via packed fma.rn.f32x2 (2 FMA/instr).
#define GEMM_SMEM_BYTES ((128 * 132 + 128 * 68) * 4)
__global__ void k_gemm(const float* __restrict__ W, int E) {
    extern __shared__ float sm[];
    float (*ws)[132] = (float(*)[132])sm;
    float (*xs)[68]  = (float(*)[68])(sm + 128 * 132);
    int tid = threadIdx.x;

    for (int i = tid; i < 128 * 32; i += 256) {
        int k = i >> 5, c4 = i & 31;
        float4 v = ((const float4*)W)[i];
        ws[k][c4 * 4 + 0] = v.x; ws[k][c4 * 4 + 1] = v.y;
        ws[k][c4 * 4 + 2] = v.z; ws[k][c4 * 4 + 3] = v.w;
    }
    int r0 = blockIdx.x * 64;
    for (int i = tid; i < 64 * 32; i += 256) {
        int r = i >> 5, k4 = i & 31;
        int row = r0 + r;
        float4 v = make_float4(0.f, 0.f, 0.f, 0.f);
        if (row < E) v = ((const float4*)g_eaccum)[(size_t)row * 32 + k4];
        xs[k4 * 4 + 0][r] = v.x; xs[k4 * 4 + 1][r] = v.y;
        xs[k4 * 4 + 2][r] = v.z; xs[k4 * 4 + 3][r] = v.w;
    }
    __syncthreads();

    int tx = tid & 15, ty = tid >> 4;
    unsigned long long acc[4][4];   // acc[i][p] = outputs (j=2p, j=2p+1) for row i
#pragma unroll
    for (int i = 0; i < 4; i++)
#pragma unroll
        for (int p = 0; p < 4; p++) acc[i][p] = 0ull;

#pragma unroll 4
    for (int k = 0; k < 128; k++) {
        float a4[4];
        *(float4*)&a4[0] = *(const float4*)&xs[k][ty * 4];
        float4 b0 = *(const float4*)&ws[k][tx * 8];
        float4 b1 = *(const float4*)&ws[k][tx * 8 + 4];
        unsigned long long bp[4];
        bp[0] = pack2(b0.x, b0.y); bp[1] = pack2(b0.z, b0.w);
        bp[2] = pack2(b1.x, b1.y); bp[3] = pack2(b1.z, b1.w);
#pragma unroll
        for (int i = 0; i < 4; i++) {
            unsigned long long ap = pack2(a4[i], a4[i]);
#pragma unroll
            for (int p = 0; p < 4; p++) fma2(acc[i][p], ap, bp[p]);
        }
    }

#pragma unroll
    for (int i = 0; i < 4; i++) {
        int row = r0 + ty * 4 + i;
        if (row < E) {
            ulonglong2* dst = (ulonglong2*)&g_eaccum[(size_t)row * 128 + tx * 8];
            dst[0] = make_ulonglong2(acc[i][0], acc[i][1]);
            dst[1] = make_ulonglong2(acc[i][2], acc[i][3]);
        }
    }
}

// Phase B: warp per node (grid-stride). Gather e_featW rows, D^-1 from hw on the
// fly (lane-parallel + warp reduce), add bias, write out, accumulate BN partials.
__global__ void k_node_gather(const float* __restrict__ hw, const float* __restrict__ b,
                              float* __restrict__ out, int N) {
    int lane = threadIdx.x & 31;
    int gwarp = (int)((blockIdx.x * blockDim.x + threadIdx.x) >> 5);
    int nw = (int)((gridDim.x * blockDim.x) >> 5);
    float4 bc = ((const float4*)b)[lane];
    float4 s1 = make_float4(0.f, 0.f, 0.f, 0.f);
    float4 s2 = make_float4(0.f, 0.f, 0.f, 0.f);

    for (int v = gwarp; v < N; v += nw) {
        int start = (v == 0) ? 0 : g_startN[v - 1];
        int end = g_startN[v];
        float4 acc = make_float4(0.f, 0.f, 0.f, 0.f);
        float wlocal = 0.f;
        int i = start;
        for (; i + 32 <= end; i += 32) {
            int my = g_csrB[i + lane];
            wlocal += __ldg(&hw[my]);
#pragma unroll 8
            for (int j = 0; j < 32; j++) {
                int e = __shfl_sync(0xffffffffu, my, j);
                float4 t = ((const float4*)g_eaccum)[(size_t)e * 32 + lane];
                acc.x += t.x; acc.y += t.y; acc.z += t.z; acc.w += t.w;
            }
        }
        int rem = end - i;
        if (rem > 0) {
            int my = (lane < rem) ? g_csrB[i + lane] : 0;
            if (lane < rem) wlocal += __ldg(&hw[my]);
#pragma unroll 4
            for (int j = 0; j < rem; j++) {
                int e = __shfl_sync(0xffffffffu, my, j);
                float4 t = ((const float4*)g_eaccum)[(size_t)e * 32 + lane];
                acc.x += t.x; acc.y += t.y; acc.z += t.z; acc.w += t.w;
            }
        }
        float wsum = wlocal;
#pragma unroll
        for (int o = 16; o > 0; o >>= 1) wsum += __shfl_xor_sync(0xffffffffu, wsum, o);
        float dinv = wsum > 0.f ? 1.f / wsum : 0.f;
        float4 val;
        val.x = acc.x * dinv + bc.x; val.y = acc.y * dinv + bc.y;
        val.z = acc.z * dinv + bc.z; val.w = acc.w * dinv + bc.w;
        ((float4*)out)[(size_t)v * 32 + lane] = val;
        s1.x += val.x; s1.y += val.y; s1.z += val.z; s1.w += val.w;
        s2.x += val.x * val.x; s2.y += val.y * val.y;
        s2.z += val.z * val.z; s2.w += val.w * val.w;
    }

    __shared__ float sh1[128], sh2[128];
    int tid = threadIdx.x;
    if (tid < 128) { sh1[tid] = 0.f; sh2[tid] = 0.f; }
    __syncthreads();
    int c0 = lane * 4;
    atomicAdd(&sh1[c0 + 0], s1.x); atomicAdd(&sh1[c0 + 1], s1.y);
    atomicAdd(&sh1[c0 + 2], s1.z); atomicAdd(&sh1[c0 + 3], s1.w);
    atomicAdd(&sh2[c0 + 0], s2.x); atomicAdd(&sh2[c0 + 1], s2.y);
    atomicAdd(&sh2[c0 + 2], s2.z); atomicAdd(&sh2[c0 + 3], s2.w);
    __syncthreads();
    if (tid < 128) {
        int slot = blockIdx.x & 31;
        atomicAdd(&g_sum[slot * 128 + tid],   (double)sh1[tid]);
        atomicAdd(&g_sumsq[slot * 128 + tid], (double)sh2[tid]);
    }
}

__global__ void k_bnprep(const float* __restrict__ gamma, const float* __restrict__ beta, int N) {
    int c = threadIdx.x;
    double s = 0.0, q = 0.0;
    for (int k = 0; k < 32; k++) { s += g_sum[k * 128 + c]; q += g_sumsq[k * 128 + c]; }
    double mean = s / (double)N;
    double var  = q / (double)N - mean * mean;
    float rstd = rsqrtf((float)var + 1e-5f);
    float sc = rstd * gamma[c];
    g_scale[c] = sc;
    g_shift[c] = beta[c] - (float)mean * sc;
}

__global__ void k_bnsilu(float* __restrict__ out, long n4) {
    long i = (long)blockIdx.x * blockDim.x + threadIdx.x;
    if (i >= n4) return;
    int c4 = (int)(i & 31);
    float4 v = ((float4*)out)[i];
    float r[4] = {v.x, v.y, v.z, v.w};
#pragma unroll
    for (int j = 0; j < 4; j++) {
        int c = c4 * 4 + j;
        float o = r[j] * g_scale[c] + g_shift[c];
        r[j] = o * (1.f / (1.f + __expf(-o)));
    }
    ((float4*)out)[i] = make_float4(r[0], r[1], r[2], r[3]);
}

// ---------------- launcher ----------------
extern "C" void kernel_launch(void* const* d_in, const int* in_sizes, int n_in,
                              void* d_out, int out_size) {
    const float* x     = (const float*)d_in[0];
    const void*  hidx  = d_in[1];
    const float* hw    = (const float*)d_in[2];
    const float* W     = (const float*)d_in[3];
    const float* b     = (const float*)d_in[4];
    const float* gamma = (const float*)d_in[5];
    const float* beta  = (const float*)d_in[6];
    float* out = (float*)d_out;

    int N   = in_sizes[0] / C;
    int nnz = in_sizes[1] / 2;
    int E   = in_sizes[2];

    void *p_cE, *p_cN, *p_s, *p_sq, *p_stE, *p_stN, *p_bE, *p_bN;
    cudaGetSymbolAddress(&p_cE,  g_cntE);
    cudaGetSymbolAddress(&p_cN,  g_cntN);
    cudaGetSymbolAddress(&p_s,   g_sum);
    cudaGetSymbolAddress(&p_sq,  g_sumsq);
    cudaGetSymbolAddress(&p_stE, g_startE);
    cudaGetSymbolAddress(&p_stN, g_startN);
    cudaGetSymbolAddress(&p_bE,  g_bsumE);
    cudaGetSymbolAddress(&p_bN,  g_bsumN);

    // fresh fork/join objects each call (host-side only; intentionally leaked —
    // kernel_launch is invoked only a handful of times, never during replay)
    cudaStream_t s2;
    cudaEvent_t evFork, evJoin;
    cudaStreamCreateWithFlags(&s2, cudaStreamNonBlocking);
    cudaEventCreateWithFlags(&evFork, cudaEventDisableTiming);
    cudaEventCreateWithFlags(&evJoin, cudaEventDisableTiming);

    int nbE = (E + SCAN_TILE - 1) / SCAN_TILE;
    int nbN = (N + SCAN_TILE - 1) / SCAN_TILE;

    // ---- main stream: edge chain ----
    cudaMemsetAsync(p_cE, 0, (size_t)E * sizeof(int), 0);
    k_detect<<<1, 32>>>((const unsigned*)hidx);
    cudaEventRecord(evFork, 0);

    k_countE<<<(nnz + 255) / 256, 256>>>(hidx, nnz);
    k_scan_local<<<nbE, 1024>>>((const int*)p_cE, (int*)p_stE, (int*)p_bE, E);
    k_scan_add<<<nbE, 1024>>>((int*)p_stE, (const int*)p_bE, E);
    k_buildE<<<(nnz + 255) / 256, 256>>>(hidx, nnz);
    k_edge_gather<<<(E + 7) / 8, 256>>>(x, E);
    cudaFuncSetAttribute(k_gemm, cudaFuncAttributeMaxDynamicSharedMemorySize, GEMM_SMEM_BYTES);
    k_gemm<<<(E + 63) / 64, 256, GEMM_SMEM_BYTES>>>(W, E);

    // ---- stream 2: node chain (joins capture via evFork) ----
    cudaStreamWaitEvent(s2, evFork, 0);
    cudaMemsetAsync(p_cN, 0, (size_t)N * sizeof(int), s2);
    cudaMemsetAsync(p_s,  0, 32 * C * sizeof(double), s2);
    cudaMemsetAsync(p_sq, 0, 32 * C * sizeof(double), s2);
    k_countN<<<(nnz + 255) / 256, 256, 0, s2>>>(hidx, nnz);
    k_scan_local<<<nbN, 1024, 0, s2>>>((const int*)p_cN, (int*)p_stN, (int*)p_bN, N);
    k_scan_add<<<nbN, 1024, 0, s2>>>((int*)p_stN, (const int*)p_bN, N);
    k_buildN<<<(nnz + 255) / 256, 256, 0, s2>>>(hidx, nnz);
    cudaEventRecord(evJoin, s2);

    // ---- join, then node gather + BN + SiLU on main ----
    cudaStreamWaitEvent(0, evJoin, 0);
    k_node_gather<<<2048, 256>>>(hw, b, out, N);
    k_bnprep<<<1, 128>>>(gamma, beta, N);
    long n4 = (long)N * 32;
    k_bnsilu<<<(int)((n4 + 255) / 256), 256>>>(out, n4);
}

// round 6
// speedup vs baseline: 1.8395x; 1.0204x over previous
#include <cuda_runtime.h>
#include <cuda_fp16.h>
#include <cstdint>
#include <math.h>

#define C 128
#define MAXN 100000
#define MAXE 50000
#define MAXNNZ 1600000
#define SCAN_TILE 4096

// ---------------- scratch (static device globals; no allocation) ----------------
__device__ __half g_xh[(size_t)MAXN * C];       // x converted to fp16
__device__ __half g_eah[(size_t)MAXE * C];      // edge features fp16 (pre-GEMM)
__device__ __half g_eahW[(size_t)MAXE * C];     // edge features after GEMM (fp16)
__device__ int    g_cntE[MAXE];
__device__ int    g_cntN[MAXN];
__device__ int    g_startE[MAXE];               // excl-scan, mutated into segment ENDs by build
__device__ int    g_startN[MAXN];
__device__ int    g_csrA[MAXNNZ];               // node ids grouped by edge
__device__ int    g_csrB[MAXNNZ];               // edge ids grouped by node
__device__ int    g_bsumE[64];
__device__ int    g_bsumN[64];
__device__ double g_sum[32 * C];                // slotted BN partials
__device__ double g_sumsq[32 * C];
__device__ float  g_scale[C];
__device__ float  g_shift[C];
__device__ int    g_is64;

// ---------------- helpers ----------------
__device__ __forceinline__ long ldidx(const void* base, long i) {
    if (g_is64) return (long)((const long long*)base)[i];
    return (long)((const int*)base)[i];
}

__device__ __forceinline__ void fma2(unsigned long long& d, unsigned long long a, unsigned long long b) {
    asm("fma.rn.f32x2 %0, %1, %2, %0;" : "+l"(d) : "l"(a), "l"(b));
}
__device__ __forceinline__ unsigned long long pack2(float lo, float hi) {
    unsigned long long r;
    asm("mov.b64 %0, {%1, %2};" : "=l"(r) : "f"(lo), "f"(hi));
    return r;
}
__device__ __forceinline__ float2 unpack2(unsigned long long v) {
    float lo, hi;
    asm("mov.b64 {%0, %1}, %2;" : "=f"(lo), "=f"(hi) : "l"(v));
    return make_float2(lo, hi);
}

// accumulate 8 fp16 channels (uint4) into float acc[8]
__device__ __forceinline__ void acc_half8(float* acc, uint4 raw) {
    __half2 h0 = *(__half2*)&raw.x, h1 = *(__half2*)&raw.y;
    __half2 h2 = *(__half2*)&raw.z, h3 = *(__half2*)&raw.w;
    float2 f0 = __half22float2(h0), f1 = __half22float2(h1);
    float2 f2 = __half22float2(h2), f3 = __half22float2(h3);
    acc[0] += f0.x; acc[1] += f0.y; acc[2] += f1.x; acc[3] += f1.y;
    acc[4] += f2.x; acc[5] += f2.y; acc[6] += f3.x; acc[7] += f3.y;
}

// ---------------- kernels ----------------

__global__ void k_detect(const unsigned* p) {
    if (threadIdx.x == 0) {
        int is64 = 1;
        for (int i = 0; i < 64; i++)
            if (p[2 * i + 1] != 0u) { is64 = 0; break; }
        g_is64 = is64;
    }
}

// convert x fp32 -> fp16 (4 elems per thread)
__global__ void k_convert_x(const float* __restrict__ x, long n4) {
    long i = (long)blockIdx.x * blockDim.x + threadIdx.x;
    if (i >= n4) return;
    float4 v = ((const float4*)x)[i];
    uint2 o;
    __half2 h0 = __floats2half2_rn(v.x, v.y);
    __half2 h1 = __floats2half2_rn(v.z, v.w);
    o.x = *(unsigned*)&h0; o.y = *(unsigned*)&h1;
    ((uint2*)g_xh)[i] = o;
}

__global__ void k_countE(const void* __restrict__ hidx, int nnz) {
    long i = (long)blockIdx.x * blockDim.x + threadIdx.x;
    if (i >= nnz) return;
    long edge = ldidx(hidx, (long)nnz + i);
    atomicAdd(&g_cntE[edge], 1);
}
__global__ void k_countN(const void* __restrict__ hidx, int nnz) {
    long i = (long)blockIdx.x * blockDim.x + threadIdx.x;
    if (i >= nnz) return;
    long node = ldidx(hidx, i);
    atomicAdd(&g_cntN[node], 1);
}

// pass 1: block-local exclusive scan of one 4096-elem tile + record block total
__global__ void k_scan_local(const int* __restrict__ src, int* __restrict__ dst,
                             int* __restrict__ bsum, int n) {
    __shared__ int warpsums[32];
    int tid = threadIdx.x, lane = tid & 31, wid = tid >> 5;
    int i0 = blockIdx.x * SCAN_TILE + tid * 4;

    int4 v = make_int4(0, 0, 0, 0);
    if (i0 + 3 < n) v = *(const int4*)(src + i0);
    else {
        if (i0 < n)     v.x = src[i0];
        if (i0 + 1 < n) v.y = src[i0 + 1];
        if (i0 + 2 < n) v.z = src[i0 + 2];
    }
    int t = v.x + v.y + v.z + v.w;
    int s = t;
    for (int o = 1; o < 32; o <<= 1) {
        int u = __shfl_up_sync(0xffffffffu, s, o);
        if (lane >= o) s += u;
    }
    if (lane == 31) warpsums[wid] = s;
    __syncthreads();
    if (wid == 0) {
        int ws = warpsums[lane];
        for (int o = 1; o < 32; o <<= 1) {
            int u = __shfl_up_sync(0xffffffffu, ws, o);
            if (lane >= o) ws += u;
        }
        warpsums[lane] = ws;
        if (lane == 31) bsum[blockIdx.x] = ws;
    }
    __syncthreads();
    int excl = s - t + (wid > 0 ? warpsums[wid - 1] : 0);
    int4 o4;
    o4.x = excl; o4.y = excl + v.x; o4.z = excl + v.x + v.y; o4.w = excl + v.x + v.y + v.z;
    if (i0 + 3 < n) *(int4*)(dst + i0) = o4;
    else {
        if (i0 < n)     dst[i0]     = o4.x;
        if (i0 + 1 < n) dst[i0 + 1] = o4.y;
        if (i0 + 2 < n) dst[i0 + 2] = o4.z;
    }
}

// fused pass 2+3
__global__ void k_scan_add(int* __restrict__ dst, const int* __restrict__ bsum, int n) {
    __shared__ int s_off;
    int bi = blockIdx.x;
    if (threadIdx.x == 0) {
        int run = 0;
        for (int k = 0; k < bi; k++) run += bsum[k];
        s_off = run;
    }
    __syncthreads();
    int off = s_off;
    if (off == 0) return;
    int i0 = bi * SCAN_TILE + threadIdx.x * 4;
    if (i0 + 3 < n) {
        int4 v = *(const int4*)(dst + i0);
        v.x += off; v.y += off; v.z += off; v.w += off;
        *(int4*)(dst + i0) = v;
    } else {
        if (i0 < n)     dst[i0]     += off;
        if (i0 + 1 < n) dst[i0 + 1] += off;
        if (i0 + 2 < n) dst[i0 + 2] += off;
    }
}

// Build CSR halves; atomicAdd on start doubles as cursor (start -> segment ENDs).
__global__ void k_buildE(const void* __restrict__ hidx, int nnz) {
    long i = (long)blockIdx.x * blockDim.x + threadIdx.x;
    if (i >= nnz) return;
    long node = ldidx(hidx, i);
    long edge = ldidx(hidx, (long)nnz + i);
    int pE = atomicAdd(&g_startE[edge], 1);
    g_csrA[pE] = (int)node;
}
__global__ void k_buildN(const void* __restrict__ hidx, int nnz) {
    long i = (long)blockIdx.x * blockDim.x + threadIdx.x;
    if (i >= nnz) return;
    long node = ldidx(hidx, i);
    long edge = ldidx(hidx, (long)nnz + i);
    int pN = atomicAdd(&g_startN[node], 1);
    g_csrB[pN] = (int)edge;
}

// Phase A: warp per edge, two entries per iteration (half-warps), 16B loads.
// lane = half*16 + c16; lane handles channels c16*8..c16*8+7 of entry 2p+half.
__global__ void k_edge_gather(int E) {
    int e = blockIdx.x * 8 + (threadIdx.x >> 5);
    if (e >= E) return;
    int lane = threadIdx.x & 31;
    int c16 = lane & 15, half = lane >> 4;
    int start = (e == 0) ? 0 : g_startE[e - 1];
    int end = g_startE[e];
    float acc[8];
#pragma unroll
    for (int k = 0; k < 8; k++) acc[k] = 0.f;

    int i = start;
    for (; i + 32 <= end; i += 32) {
        int my = g_csrA[i + lane];
#pragma unroll
        for (int p = 0; p < 16; p++) {
            int nd = __shfl_sync(0xffffffffu, my, 2 * p + half);
            acc_half8(acc, ((const uint4*)g_xh)[(size_t)nd * 16 + c16]);
        }
    }
    int rem = end - i;
    if (rem > 0) {
        int my = (lane < rem) ? g_csrA[i + lane] : 0;
        int npair = rem >> 1;
#pragma unroll 4
        for (int p = 0; p < npair; p++) {
            int nd = __shfl_sync(0xffffffffu, my, 2 * p + half);
            acc_half8(acc, ((const uint4*)g_xh)[(size_t)nd * 16 + c16]);
        }
        if (rem & 1) {
            int nd = __shfl_sync(0xffffffffu, my, rem - 1);
            if (half == 0)
                acc_half8(acc, ((const uint4*)g_xh)[(size_t)nd * 16 + c16]);
        }
    }
    // combine the two half-warps (same channels, xor-16 partner)
#pragma unroll
    for (int k = 0; k < 8; k++)
        acc[k] += __shfl_xor_sync(0xffffffffu, acc[k], 16);

    if (half == 0) {
        float binv = (end > start) ? 1.f / (float)(end - start) : 0.f;
        __half2 h0 = __floats2half2_rn(acc[0] * binv, acc[1] * binv);
        __half2 h1 = __floats2half2_rn(acc[2] * binv, acc[3] * binv);
        __half2 h2 = __floats2half2_rn(acc[4] * binv, acc[5] * binv);
        __half2 h3 = __floats2half2_rn(acc[6] * binv, acc[7] * binv);
        uint4 o;
        o.x = *(unsigned*)&h0; o.y = *(unsigned*)&h1;
        o.z = *(unsigned*)&h2; o.w = *(unsigned*)&h3;
        ((uint4*)g_eah)[(size_t)e * 16 + c16] = o;
    }
}

// GEMM: eahW[r][:] = eah[r][:] @ W.  64-row blocks, 256 threads, f32x2 4x8 tile.
#define GEMM_SMEM_BYTES ((128 * 132 + 128 * 68) * 4)
__global__ void k_gemm(const float* __restrict__ W, int E) {
    extern __shared__ float sm[];
    float (*ws)[132] = (float(*)[132])sm;
    float (*xs)[68]  = (float(*)[68])(sm + 128 * 132);
    int tid = threadIdx.x;

    for (int i = tid; i < 128 * 32; i += 256) {
        int k = i >> 5, c4 = i & 31;
        float4 v = ((const float4*)W)[i];
        ws[k][c4 * 4 + 0] = v.x; ws[k][c4 * 4 + 1] = v.y;
        ws[k][c4 * 4 + 2] = v.z; ws[k][c4 * 4 + 3] = v.w;
    }
    int r0 = blockIdx.x * 64;
    for (int i = tid; i < 64 * 32; i += 256) {
        int r = i >> 5, k4 = i & 31;
        int row = r0 + r;
        float4 v = make_float4(0.f, 0.f, 0.f, 0.f);
        if (row < E) {
            uint2 raw = ((const uint2*)g_eah)[(size_t)row * 32 + k4];
            __half2 h0 = *(__half2*)&raw.x, h1 = *(__half2*)&raw.y;
            float2 f0 = __half22float2(h0), f1 = __half22float2(h1);
            v = make_float4(f0.x, f0.y, f1.x, f1.y);
        }
        xs[k4 * 4 + 0][r] = v.x; xs[k4 * 4 + 1][r] = v.y;
        xs[k4 * 4 + 2][r] = v.z; xs[k4 * 4 + 3][r] = v.w;
    }
    __syncthreads();

    int tx = tid & 15, ty = tid >> 4;
    unsigned long long acc[4][4];
#pragma unroll
    for (int i = 0; i < 4; i++)
#pragma unroll
        for (int p = 0; p < 4; p++) acc[i][p] = 0ull;

#pragma unroll 4
    for (int k = 0; k < 128; k++) {
        float a4[4];
        *(float4*)&a4[0] = *(const float4*)&xs[k][ty * 4];
        float4 b0 = *(const float4*)&ws[k][tx * 8];
        float4 b1 = *(const float4*)&ws[k][tx * 8 + 4];
        unsigned long long bp[4];
        bp[0] = pack2(b0.x, b0.y); bp[1] = pack2(b0.z, b0.w);
        bp[2] = pack2(b1.x, b1.y); bp[3] = pack2(b1.z, b1.w);
#pragma unroll
        for (int i = 0; i < 4; i++) {
            unsigned long long ap = pack2(a4[i], a4[i]);
#pragma unroll
            for (int p = 0; p < 4; p++) fma2(acc[i][p], ap, bp[p]);
        }
    }

#pragma unroll
    for (int i = 0; i < 4; i++) {
        int row = r0 + ty * 4 + i;
        if (row < E) {
            uint4 o;
            float2 f0 = unpack2(acc[i][0]), f1 = unpack2(acc[i][1]);
            float2 f2 = unpack2(acc[i][2]), f3 = unpack2(acc[i][3]);
            __half2 h0 = __floats2half2_rn(f0.x, f0.y);
            __half2 h1 = __floats2half2_rn(f1.x, f1.y);
            __half2 h2 = __floats2half2_rn(f2.x, f2.y);
            __half2 h3 = __floats2half2_rn(f3.x, f3.y);
            o.x = *(unsigned*)&h0; o.y = *(unsigned*)&h1;
            o.z = *(unsigned*)&h2; o.w = *(unsigned*)&h3;
            *(uint4*)&g_eahW[(size_t)row * 128 + tx * 8] = o;
        }
    }
}

// Phase B: warp per node (grid-stride), two entries per iteration, 16B loads.
__global__ void k_node_gather(const float* __restrict__ hw, const float* __restrict__ b,
                              float* __restrict__ out, int N) {
    int lane = threadIdx.x & 31;
    int c16 = lane & 15, half = lane >> 4;
    int gwarp = (int)((blockIdx.x * blockDim.x + threadIdx.x) >> 5);
    int nw = (int)((gridDim.x * blockDim.x) >> 5);
    float4 b0 = ((const float4*)b)[c16 * 2];
    float4 b1 = ((const float4*)b)[c16 * 2 + 1];
    float s1v[8], s2v[8];
#pragma unroll
    for (int k = 0; k < 8; k++) { s1v[k] = 0.f; s2v[k] = 0.f; }

    for (int v = gwarp; v < N; v += nw) {
        int start = (v == 0) ? 0 : g_startN[v - 1];
        int end = g_startN[v];
        float acc[8];
#pragma unroll
        for (int k = 0; k < 8; k++) acc[k] = 0.f;
        float wlocal = 0.f;
        int i = start;
        for (; i + 32 <= end; i += 32) {
            int my = g_csrB[i + lane];
            wlocal += __ldg(&hw[my]);
#pragma unroll
            for (int p = 0; p < 16; p++) {
                int e = __shfl_sync(0xffffffffu, my, 2 * p + half);
                acc_half8(acc, ((const uint4*)g_eahW)[(size_t)e * 16 + c16]);
            }
        }
        int rem = end - i;
        if (rem > 0) {
            int my = (lane < rem) ? g_csrB[i + lane] : 0;
            if (lane < rem) wlocal += __ldg(&hw[my]);
            int npair = rem >> 1;
#pragma unroll 4
            for (int p = 0; p < npair; p++) {
                int e = __shfl_sync(0xffffffffu, my, 2 * p + half);
                acc_half8(acc, ((const uint4*)g_eahW)[(size_t)e * 16 + c16]);
            }
            if (rem & 1) {
                int e = __shfl_sync(0xffffffffu, my, rem - 1);
                if (half == 0)
                    acc_half8(acc, ((const uint4*)g_eahW)[(size_t)e * 16 + c16]);
            }
        }
#pragma unroll
        for (int k = 0; k < 8; k++)
            acc[k] += __shfl_xor_sync(0xffffffffu, acc[k], 16);
        float wsum = wlocal;
#pragma unroll
        for (int o = 16; o > 0; o >>= 1) wsum += __shfl_xor_sync(0xffffffffu, wsum, o);

        if (half == 0) {
            float dinv = wsum > 0.f ? 1.f / wsum : 0.f;
            float val[8];
            val[0] = acc[0] * dinv + b0.x; val[1] = acc[1] * dinv + b0.y;
            val[2] = acc[2] * dinv + b0.z; val[3] = acc[3] * dinv + b0.w;
            val[4] = acc[4] * dinv + b1.x; val[5] = acc[5] * dinv + b1.y;
            val[6] = acc[6] * dinv + b1.z; val[7] = acc[7] * dinv + b1.w;
            float4* dst = (float4*)&out[(size_t)v * 128 + c16 * 8];
            dst[0] = make_float4(val[0], val[1], val[2], val[3]);
            dst[1] = make_float4(val[4], val[5], val[6], val[7]);
#pragma unroll
            for (int k = 0; k < 8; k++) {
                s1v[k] += val[k];
                s2v[k] += val[k] * val[k];
            }
        }
    }

    __shared__ float sh1[128], sh2[128];
    int tid = threadIdx.x;
    if (tid < 128) { sh1[tid] = 0.f; sh2[tid] = 0.f; }
    __syncthreads();
    if (half == 0) {
#pragma unroll
        for (int k = 0; k < 8; k++) {
            atomicAdd(&sh1[c16 * 8 + k], s1v[k]);
            atomicAdd(&sh2[c16 * 8 + k], s2v[k]);
        }
    }
    __syncthreads();
    if (tid < 128) {
        int slot = blockIdx.x & 31;
        atomicAdd(&g_sum[slot * 128 + tid],   (double)sh1[tid]);
        atomicAdd(&g_sumsq[slot * 128 + tid], (double)sh2[tid]);
    }
}

__global__ void k_bnprep(const float* __restrict__ gamma, const float* __restrict__ beta, int N) {
    int c = threadIdx.x;
    double s = 0.0, q = 0.0;
    for (int k = 0; k < 32; k++) { s += g_sum[k * 128 + c]; q += g_sumsq[k * 128 + c]; }
    double mean = s / (double)N;
    double var  = q / (double)N - mean * mean;
    float rstd = rsqrtf((float)var + 1e-5f);
    float sc = rstd * gamma[c];
    g_scale[c] = sc;
    g_shift[c] = beta[c] - (float)mean * sc;
}

__global__ void k_bnsilu(float* __restrict__ out, long n4) {
    long i = (long)blockIdx.x * blockDim.x + threadIdx.x;
    if (i >= n4) return;
    int c4 = (int)(i & 31);
    float4 v = ((float4*)out)[i];
    float r[4] = {v.x, v.y, v.z, v.w};
#pragma unroll
    for (int j = 0; j < 4; j++) {
        int c = c4 * 4 + j;
        float o = r[j] * g_scale[c] + g_shift[c];
        r[j] = o * (1.f / (1.f + __expf(-o)));
    }
    ((float4*)out)[i] = make_float4(r[0], r[1], r[2], r[3]);
}

// ---------------- launcher ----------------
extern "C" void kernel_launch(void* const* d_in, const int* in_sizes, int n_in,
                              void* d_out, int out_size) {
    const float* x     = (const float*)d_in[0];
    const void*  hidx  = d_in[1];
    const float* hw    = (const float*)d_in[2];
    const float* W     = (const float*)d_in[3];
    const float* b     = (const float*)d_in[4];
    const float* gamma = (const float*)d_in[5];
    const float* beta  = (const float*)d_in[6];
    float* out = (float*)d_out;

    int N   = in_sizes[0] / C;
    int nnz = in_sizes[1] / 2;
    int E   = in_sizes[2];

    void *p_cE, *p_cN, *p_s, *p_sq, *p_stE, *p_stN, *p_bE, *p_bN;
    cudaGetSymbolAddress(&p_cE,  g_cntE);
    cudaGetSymbolAddress(&p_cN,  g_cntN);
    cudaGetSymbolAddress(&p_s,   g_sum);
    cudaGetSymbolAddress(&p_sq,  g_sumsq);
    cudaGetSymbolAddress(&p_stE, g_startE);
    cudaGetSymbolAddress(&p_stN, g_startN);
    cudaGetSymbolAddress(&p_bE,  g_bsumE);
    cudaGetSymbolAddress(&p_bN,  g_bsumN);

    // one extra stream + events — identical resource footprint to the passing R4
    cudaStream_t s2;
    cudaEvent_t evFork, evJoin, evX;
    cudaStreamCreateWithFlags(&s2, cudaStreamNonBlocking);
    cudaEventCreateWithFlags(&evFork, cudaEventDisableTiming);
    cudaEventCreateWithFlags(&evJoin, cudaEventDisableTiming);
    cudaEventCreateWithFlags(&evX, cudaEventDisableTiming);

    int nbE = (E + SCAN_TILE - 1) / SCAN_TILE;
    int nbN = (N + SCAN_TILE - 1) / SCAN_TILE;

    // ---- main stream head ----
    cudaMemsetAsync(p_cE, 0, (size_t)E * sizeof(int), 0);
    k_detect<<<1, 32>>>((const unsigned*)hidx);
    cudaEventRecord(evFork, 0);

    // ---- main stream: edge chain ----
    k_countE<<<(nnz + 255) / 256, 256>>>(hidx, nnz);
    k_scan_local<<<nbE, 1024>>>((const int*)p_cE, (int*)p_stE, (int*)p_bE, E);
    k_scan_add<<<nbE, 1024>>>((int*)p_stE, (const int*)p_bE, E);
    k_buildE<<<(nnz + 255) / 256, 256>>>(hidx, nnz);

    // ---- stream 2: convert_x first (overlaps edge CSR build), then node chain ----
    cudaStreamWaitEvent(s2, evFork, 0);
    {
        long n4 = (long)N * 32;
        k_convert_x<<<(int)((n4 + 255) / 256), 256, 0, s2>>>(x, n4);
    }
    cudaEventRecord(evX, s2);
    cudaMemsetAsync(p_cN, 0, (size_t)N * sizeof(int), s2);
    cudaMemsetAsync(p_s,  0, 32 * C * sizeof(double), s2);
    cudaMemsetAsync(p_sq, 0, 32 * C * sizeof(double), s2);
    k_countN<<<(nnz + 255) / 256, 256, 0, s2>>>(hidx, nnz);
    k_scan_local<<<nbN, 1024, 0, s2>>>((const int*)p_cN, (int*)p_stN, (int*)p_bN, N);
    k_scan_add<<<nbN, 1024, 0, s2>>>((int*)p_stN, (const int*)p_bN, N);
    k_buildN<<<(nnz + 255) / 256, 256, 0, s2>>>(hidx, nnz);
    cudaEventRecord(evJoin, s2);

    // ---- main stream: gathers + GEMM ----
    cudaStreamWaitEvent(0, evX, 0);
    k_edge_gather<<<(E + 7) / 8, 256>>>(E);
    cudaFuncSetAttribute(k_gemm, cudaFuncAttributeMaxDynamicSharedMemorySize, GEMM_SMEM_BYTES);
    k_gemm<<<(E + 63) / 64, 256, GEMM_SMEM_BYTES>>>(W, E);

    cudaStreamWaitEvent(0, evJoin, 0);
    k_node_gather<<<2048, 256>>>(hw, b, out, N);
    k_bnprep<<<1, 128>>>(gamma, beta, N);
    long n4o = (long)N * 32;
    k_bnsilu<<<(int)((n4o + 255) / 256), 256>>>(out, n4o);
}

// round 7
// speedup vs baseline: 1.8979x; 1.0317x over previous
#include <cuda_runtime.h>
#include <cuda_fp16.h>
#include <cstdint>
#include <math.h>

#define C 128
#define MAXN 100000
#define MAXE 50000
#define MAXNNZ 1600000
#define SCAN_TILE 4096

// ---------------- scratch (static device globals; no allocation) ----------------
__device__ __half g_xh[(size_t)MAXN * C];       // x converted to fp16
__device__ __half g_eah[(size_t)MAXE * C];      // edge features fp16 (pre-GEMM)
__device__ __half g_eahW[(size_t)MAXE * C];     // edge features after GEMM (fp16)
__device__ int    g_cntE[MAXE];
__device__ int    g_cntN[MAXN];
__device__ int    g_startE[MAXE];               // excl-scan, mutated into segment ENDs by build
__device__ int    g_startN[MAXN];
__device__ int    g_csrA[MAXNNZ];               // node ids grouped by edge
__device__ int    g_csrB[MAXNNZ];               // edge ids grouped by node
__device__ int    g_bsumE[64];
__device__ int    g_bsumN[64];
__device__ double g_sum[32 * C];                // slotted BN partials
__device__ double g_sumsq[32 * C];
__device__ float  g_scale[C];
__device__ float  g_shift[C];
__device__ int    g_is64;

// ---------------- helpers ----------------
__device__ __forceinline__ void fma2(unsigned long long& d, unsigned long long a, unsigned long long b) {
    asm("fma.rn.f32x2 %0, %1, %2, %0;" : "+l"(d) : "l"(a), "l"(b));
}
__device__ __forceinline__ unsigned long long pack2(float lo, float hi) {
    unsigned long long r;
    asm("mov.b64 %0, {%1, %2};" : "=l"(r) : "f"(lo), "f"(hi));
    return r;
}
__device__ __forceinline__ float2 unpack2(unsigned long long v) {
    float lo, hi;
    asm("mov.b64 {%0, %1}, %2;" : "=f"(lo), "=f"(hi) : "l"(v));
    return make_float2(lo, hi);
}

// load a pair of indices (entries 2t, 2t+1) from row starting at element offset rowoff
__device__ __forceinline__ void ldidx_pair(const void* base, long rowoff, long t,
                                           bool both, int& a, int& b) {
    if (g_is64) {
        if (both) {
            longlong2 v = ((const longlong2*)((const long long*)base + rowoff))[t];
            a = (int)v.x; b = (int)v.y;
        } else {
            a = (int)((const long long*)base)[rowoff + 2 * t];
            b = 0;
        }
    } else {
        if (both) {
            int2 v = ((const int2*)((const int*)base + rowoff))[t];
            a = v.x; b = v.y;
        } else {
            a = ((const int*)base)[rowoff + 2 * t];
            b = 0;
        }
    }
}

// accumulate 4 fp16 channels (uint2) into float4 acc
__device__ __forceinline__ void acc_half4(float4& acc, uint2 raw) {
    __half2 h0 = *(__half2*)&raw.x, h1 = *(__half2*)&raw.y;
    float2 f0 = __half22float2(h0), f1 = __half22float2(h1);
    acc.x += f0.x; acc.y += f0.y; acc.z += f1.x; acc.w += f1.y;
}

// ---------------- kernels ----------------

__global__ void k_detect(const unsigned* p) {
    if (threadIdx.x == 0) {
        int is64 = 1;
        for (int i = 0; i < 64; i++)
            if (p[2 * i + 1] != 0u) { is64 = 0; break; }
        g_is64 = is64;
    }
}

// convert x fp32 -> fp16 (4 elems per thread)
__global__ void k_convert_x(const float* __restrict__ x, long n4) {
    long i = (long)blockIdx.x * blockDim.x + threadIdx.x;
    if (i >= n4) return;
    float4 v = ((const float4*)x)[i];
    uint2 o;
    __half2 h0 = __floats2half2_rn(v.x, v.y);
    __half2 h1 = __floats2half2_rn(v.z, v.w);
    o.x = *(unsigned*)&h0; o.y = *(unsigned*)&h1;
    ((uint2*)g_xh)[i] = o;
}

// counts: 2 entries per thread via wide index loads
__global__ void k_countE(const void* __restrict__ hidx, int nnz) {
    long t = (long)blockIdx.x * blockDim.x + threadIdx.x;
    long i0 = 2 * t;
    if (i0 >= nnz) return;
    bool both = (i0 + 1 < nnz);
    int e0, e1;
    ldidx_pair(hidx, (long)nnz, t, both, e0, e1);
    atomicAdd(&g_cntE[e0], 1);
    if (both) atomicAdd(&g_cntE[e1], 1);
}
__global__ void k_countN(const void* __restrict__ hidx, int nnz) {
    long t = (long)blockIdx.x * blockDim.x + threadIdx.x;
    long i0 = 2 * t;
    if (i0 >= nnz) return;
    bool both = (i0 + 1 < nnz);
    int n0, n1;
    ldidx_pair(hidx, 0, t, both, n0, n1);
    atomicAdd(&g_cntN[n0], 1);
    if (both) atomicAdd(&g_cntN[n1], 1);
}

// pass 1: block-local exclusive scan of one 4096-elem tile + record block total
__global__ void k_scan_local(const int* __restrict__ src, int* __restrict__ dst,
                             int* __restrict__ bsum, int n) {
    __shared__ int warpsums[32];
    int tid = threadIdx.x, lane = tid & 31, wid = tid >> 5;
    int i0 = blockIdx.x * SCAN_TILE + tid * 4;

    int4 v = make_int4(0, 0, 0, 0);
    if (i0 + 3 < n) v = *(const int4*)(src + i0);
    else {
        if (i0 < n)     v.x = src[i0];
        if (i0 + 1 < n) v.y = src[i0 + 1];
        if (i0 + 2 < n) v.z = src[i0 + 2];
    }
    int t = v.x + v.y + v.z + v.w;
    int s = t;
    for (int o = 1; o < 32; o <<= 1) {
        int u = __shfl_up_sync(0xffffffffu, s, o);
        if (lane >= o) s += u;
    }
    if (lane == 31) warpsums[wid] = s;
    __syncthreads();
    if (wid == 0) {
        int ws = warpsums[lane];
        for (int o = 1; o < 32; o <<= 1) {
            int u = __shfl_up_sync(0xffffffffu, ws, o);
            if (lane >= o) ws += u;
        }
        warpsums[lane] = ws;
        if (lane == 31) bsum[blockIdx.x] = ws;
    }
    __syncthreads();
    int excl = s - t + (wid > 0 ? warpsums[wid - 1] : 0);
    int4 o4;
    o4.x = excl; o4.y = excl + v.x; o4.z = excl + v.x + v.y; o4.w = excl + v.x + v.y + v.z;
    if (i0 + 3 < n) *(int4*)(dst + i0) = o4;
    else {
        if (i0 < n)     dst[i0]     = o4.x;
        if (i0 + 1 < n) dst[i0 + 1] = o4.y;
        if (i0 + 2 < n) dst[i0 + 2] = o4.z;
    }
}

// fused pass 2+3
__global__ void k_scan_add(int* __restrict__ dst, const int* __restrict__ bsum, int n) {
    __shared__ int s_off;
    int bi = blockIdx.x;
    if (threadIdx.x == 0) {
        int run = 0;
        for (int k = 0; k < bi; k++) run += bsum[k];
        s_off = run;
    }
    __syncthreads();
    int off = s_off;
    if (off == 0) return;
    int i0 = bi * SCAN_TILE + threadIdx.x * 4;
    if (i0 + 3 < n) {
        int4 v = *(const int4*)(dst + i0);
        v.x += off; v.y += off; v.z += off; v.w += off;
        *(int4*)(dst + i0) = v;
    } else {
        if (i0 < n)     dst[i0]     += off;
        if (i0 + 1 < n) dst[i0 + 1] += off;
        if (i0 + 2 < n) dst[i0 + 2] += off;
    }
}

// Build CSR halves (2 entries/thread); atomicAdd on start doubles as cursor.
__global__ void k_buildE(const void* __restrict__ hidx, int nnz) {
    long t = (long)blockIdx.x * blockDim.x + threadIdx.x;
    long i0 = 2 * t;
    if (i0 >= nnz) return;
    bool both = (i0 + 1 < nnz);
    int n0, n1, e0, e1;
    ldidx_pair(hidx, 0, t, both, n0, n1);
    ldidx_pair(hidx, (long)nnz, t, both, e0, e1);
    int p0 = atomicAdd(&g_startE[e0], 1);
    g_csrA[p0] = n0;
    if (both) {
        int p1 = atomicAdd(&g_startE[e1], 1);
        g_csrA[p1] = n1;
    }
}
__global__ void k_buildN(const void* __restrict__ hidx, int nnz) {
    long t = (long)blockIdx.x * blockDim.x + threadIdx.x;
    long i0 = 2 * t;
    if (i0 >= nnz) return;
    bool both = (i0 + 1 < nnz);
    int n0, n1, e0, e1;
    ldidx_pair(hidx, 0, t, both, n0, n1);
    ldidx_pair(hidx, (long)nnz, t, both, e0, e1);
    int p0 = atomicAdd(&g_startN[n0], 1);
    g_csrB[p0] = e0;
    if (both) {
        int p1 = atomicAdd(&g_startN[n1], 1);
        g_csrB[p1] = e1;
    }
}

// Phase A: warp per edge; gather fp16 node rows (uint2/lane), fp32 accumulate,
// apply B^-1, write fp16.  (R5-proven structure)
__global__ void k_edge_gather(int E) {
    int e = blockIdx.x * 8 + (threadIdx.x >> 5);
    if (e >= E) return;
    int lane = threadIdx.x & 31;
    int start = (e == 0) ? 0 : g_startE[e - 1];
    int end = g_startE[e];
    float4 acc = make_float4(0.f, 0.f, 0.f, 0.f);
    int i = start;
    for (; i + 32 <= end; i += 32) {
        int my = g_csrA[i + lane];
#pragma unroll 8
        for (int j = 0; j < 32; j++) {
            int nd = __shfl_sync(0xffffffffu, my, j);
            acc_half4(acc, ((const uint2*)g_xh)[(size_t)nd * 32 + lane]);
        }
    }
    int rem = end - i;
    if (rem > 0) {
        int my = (lane < rem) ? g_csrA[i + lane] : 0;
#pragma unroll 4
        for (int j = 0; j < rem; j++) {
            int nd = __shfl_sync(0xffffffffu, my, j);
            acc_half4(acc, ((const uint2*)g_xh)[(size_t)nd * 32 + lane]);
        }
    }
    float binv = (end > start) ? 1.f / (float)(end - start) : 0.f;
    __half2 h0 = __floats2half2_rn(acc.x * binv, acc.y * binv);
    __half2 h1 = __floats2half2_rn(acc.z * binv, acc.w * binv);
    uint2 o; o.x = *(unsigned*)&h0; o.y = *(unsigned*)&h1;
    ((uint2*)g_eah)[(size_t)e * 32 + lane] = o;
}

// GEMM: eahW[r][:] = eah[r][:] @ W.  64-row blocks, 256 threads, f32x2 4x8 tile.
#define GEMM_SMEM_BYTES ((128 * 132 + 128 * 68) * 4)
__global__ void k_gemm(const float* __restrict__ W, int E) {
    extern __shared__ float sm[];
    float (*ws)[132] = (float(*)[132])sm;
    float (*xs)[68]  = (float(*)[68])(sm + 128 * 132);
    int tid = threadIdx.x;

    for (int i = tid; i < 128 * 32; i += 256) {
        int k = i >> 5, c4 = i & 31;
        float4 v = ((const float4*)W)[i];
        ws[k][c4 * 4 + 0] = v.x; ws[k][c4 * 4 + 1] = v.y;
        ws[k][c4 * 4 + 2] = v.z; ws[k][c4 * 4 + 3] = v.w;
    }
    int r0 = blockIdx.x * 64;
    for (int i = tid; i < 64 * 32; i += 256) {
        int r = i >> 5, k4 = i & 31;
        int row = r0 + r;
        float4 v = make_float4(0.f, 0.f, 0.f, 0.f);
        if (row < E) {
            uint2 raw = ((const uint2*)g_eah)[(size_t)row * 32 + k4];
            __half2 h0 = *(__half2*)&raw.x, h1 = *(__half2*)&raw.y;
            float2 f0 = __half22float2(h0), f1 = __half22float2(h1);
            v = make_float4(f0.x, f0.y, f1.x, f1.y);
        }
        xs[k4 * 4 + 0][r] = v.x; xs[k4 * 4 + 1][r] = v.y;
        xs[k4 * 4 + 2][r] = v.z; xs[k4 * 4 + 3][r] = v.w;
    }
    __syncthreads();

    int tx = tid & 15, ty = tid >> 4;
    unsigned long long acc[4][4];
#pragma unroll
    for (int i = 0; i < 4; i++)
#pragma unroll
        for (int p = 0; p < 4; p++) acc[i][p] = 0ull;

#pragma unroll 4
    for (int k = 0; k < 128; k++) {
        float a4[4];
        *(float4*)&a4[0] = *(const float4*)&xs[k][ty * 4];
        float4 b0 = *(const float4*)&ws[k][tx * 8];
        float4 b1 = *(const float4*)&ws[k][tx * 8 + 4];
        unsigned long long bp[4];
        bp[0] = pack2(b0.x, b0.y); bp[1] = pack2(b0.z, b0.w);
        bp[2] = pack2(b1.x, b1.y); bp[3] = pack2(b1.z, b1.w);
#pragma unroll
        for (int i = 0; i < 4; i++) {
            unsigned long long ap = pack2(a4[i], a4[i]);
#pragma unroll
            for (int p = 0; p < 4; p++) fma2(acc[i][p], ap, bp[p]);
        }
    }

#pragma unroll
    for (int i = 0; i < 4; i++) {
        int row = r0 + ty * 4 + i;
        if (row < E) {
            uint4 o;
            float2 f0 = unpack2(acc[i][0]), f1 = unpack2(acc[i][1]);
            float2 f2 = unpack2(acc[i][2]), f3 = unpack2(acc[i][3]);
            __half2 h0 = __floats2half2_rn(f0.x, f0.y);
            __half2 h1 = __floats2half2_rn(f1.x, f1.y);
            __half2 h2 = __floats2half2_rn(f2.x, f2.y);
            __half2 h3 = __floats2half2_rn(f3.x, f3.y);
            o.x = *(unsigned*)&h0; o.y = *(unsigned*)&h1;
            o.z = *(unsigned*)&h2; o.w = *(unsigned*)&h3;
            *(uint4*)&g_eahW[(size_t)row * 128 + tx * 8] = o;
        }
    }
}

// Phase B: warp per node (grid-stride). Gather fp16 e_featW rows (uint2/lane),
// D^-1 from hw (lane-parallel + warp reduce), add bias, write fp32, BN partials.
__global__ void k_node_gather(const float* __restrict__ hw, const float* __restrict__ b,
                              float* __restrict__ out, int N) {
    int lane = threadIdx.x & 31;
    int gwarp = (int)((blockIdx.x * blockDim.x + threadIdx.x) >> 5);
    int nw = (int)((gridDim.x * blockDim.x) >> 5);
    float4 bc = ((const float4*)b)[lane];
    float4 s1 = make_float4(0.f, 0.f, 0.f, 0.f);
    float4 s2 = make_float4(0.f, 0.f, 0.f, 0.f);

    for (int v = gwarp; v < N; v += nw) {
        int start = (v == 0) ? 0 : g_startN[v - 1];
        int end = g_startN[v];
        float4 acc = make_float4(0.f, 0.f, 0.f, 0.f);
        float wlocal = 0.f;
        int i = start;
        for (; i + 32 <= end; i += 32) {
            int my = g_csrB[i + lane];
            wlocal += __ldg(&hw[my]);
#pragma unroll 8
            for (int j = 0; j < 32; j++) {
                int e = __shfl_sync(0xffffffffu, my, j);
                acc_half4(acc, ((const uint2*)g_eahW)[(size_t)e * 32 + lane]);
            }
        }
        int rem = end - i;
        if (rem > 0) {
            int my = (lane < rem) ? g_csrB[i + lane] : 0;
            if (lane < rem) wlocal += __ldg(&hw[my]);
#pragma unroll 4
            for (int j = 0; j < rem; j++) {
                int e = __shfl_sync(0xffffffffu, my, j);
                acc_half4(acc, ((const uint2*)g_eahW)[(size_t)e * 32 + lane]);
            }
        }
        float wsum = wlocal;
#pragma unroll
        for (int o = 16; o > 0; o >>= 1) wsum += __shfl_xor_sync(0xffffffffu, wsum, o);
        float dinv = wsum > 0.f ? 1.f / wsum : 0.f;
        float4 val;
        val.x = acc.x * dinv + bc.x; val.y = acc.y * dinv + bc.y;
        val.z = acc.z * dinv + bc.z; val.w = acc.w * dinv + bc.w;
        ((float4*)out)[(size_t)v * 32 + lane] = val;
        s1.x += val.x; s1.y += val.y; s1.z += val.z; s1.w += val.w;
        s2.x += val.x * val.x; s2.y += val.y * val.y;
        s2.z += val.z * val.z; s2.w += val.w * val.w;
    }

    __shared__ float sh1[128], sh2[128];
    int tid = threadIdx.x;
    if (tid < 128) { sh1[tid] = 0.f; sh2[tid] = 0.f; }
    __syncthreads();
    int c0 = lane * 4;
    atomicAdd(&sh1[c0 + 0], s1.x); atomicAdd(&sh1[c0 + 1], s1.y);
    atomicAdd(&sh1[c0 + 2], s1.z); atomicAdd(&sh1[c0 + 3], s1.w);
    atomicAdd(&sh2[c0 + 0], s2.x); atomicAdd(&sh2[c0 + 1], s2.y);
    atomicAdd(&sh2[c0 + 2], s2.z); atomicAdd(&sh2[c0 + 3], s2.w);
    __syncthreads();
    if (tid < 128) {
        int slot = blockIdx.x & 31;
        atomicAdd(&g_sum[slot * 128 + tid],   (double)sh1[tid]);
        atomicAdd(&g_sumsq[slot * 128 + tid], (double)sh2[tid]);
    }
}

__global__ void k_bnprep(const float* __restrict__ gamma, const float* __restrict__ beta, int N) {
    int c = threadIdx.x;
    double s = 0.0, q = 0.0;
    for (int k = 0; k < 32; k++) { s += g_sum[k * 128 + c]; q += g_sumsq[k * 128 + c]; }
    double mean = s / (double)N;
    double var  = q / (double)N - mean * mean;
    float rstd = rsqrtf((float)var + 1e-5f);
    float sc = rstd * gamma[c];
    g_scale[c] = sc;
    g_shift[c] = beta[c] - (float)mean * sc;
}

__global__ void k_bnsilu(float* __restrict__ out, long n4) {
    long i = (long)blockIdx.x * blockDim.x + threadIdx.x;
    if (i >= n4) return;
    int c4 = (int)(i & 31);
    float4 v = ((float4*)out)[i];
    float r[4] = {v.x, v.y, v.z, v.w};
#pragma unroll
    for (int j = 0; j < 4; j++) {
        int c = c4 * 4 + j;
        float o = r[j] * g_scale[c] + g_shift[c];
        r[j] = o * (1.f / (1.f + __expf(-o)));
    }
    ((float4*)out)[i] = make_float4(r[0], r[1], r[2], r[3]);
}

// ---------------- launcher ----------------
extern "C" void kernel_launch(void* const* d_in, const int* in_sizes, int n_in,
                              void* d_out, int out_size) {
    const float* x     = (const float*)d_in[0];
    const void*  hidx  = d_in[1];
    const float* hw    = (const float*)d_in[2];
    const float* W     = (const float*)d_in[3];
    const float* b     = (const float*)d_in[4];
    const float* gamma = (const float*)d_in[5];
    const float* beta  = (const float*)d_in[6];
    float* out = (float*)d_out;

    int N   = in_sizes[0] / C;
    int nnz = in_sizes[1] / 2;
    int E   = in_sizes[2];

    void *p_cE, *p_cN, *p_s, *p_sq, *p_stE, *p_stN, *p_bE, *p_bN;
    cudaGetSymbolAddress(&p_cE,  g_cntE);
    cudaGetSymbolAddress(&p_cN,  g_cntN);
    cudaGetSymbolAddress(&p_s,   g_sum);
    cudaGetSymbolAddress(&p_sq,  g_sumsq);
    cudaGetSymbolAddress(&p_stE, g_startE);
    cudaGetSymbolAddress(&p_stN, g_startN);
    cudaGetSymbolAddress(&p_bE,  g_bsumE);
    cudaGetSymbolAddress(&p_bN,  g_bsumN);

    // one extra stream + events — teardown-safe footprint (R4/R6 proven)
    cudaStream_t s2;
    cudaEvent_t evFork, evJoin, evX;
    cudaStreamCreateWithFlags(&s2, cudaStreamNonBlocking);
    cudaEventCreateWithFlags(&evFork, cudaEventDisableTiming);
    cudaEventCreateWithFlags(&evJoin, cudaEventDisableTiming);
    cudaEventCreateWithFlags(&evX, cudaEventDisableTiming);

    int nbE = (E + SCAN_TILE - 1) / SCAN_TILE;
    int nbN = (N + SCAN_TILE - 1) / SCAN_TILE;
    int npair = (nnz + 1) / 2;
    int gpair = (npair + 255) / 256;

    // ---- main stream head ----
    cudaMemsetAsync(p_cE, 0, (size_t)E * sizeof(int), 0);
    k_detect<<<1, 32>>>((const unsigned*)hidx);
    cudaEventRecord(evFork, 0);

    // ---- main stream: edge chain ----
    k_countE<<<gpair, 256>>>(hidx, nnz);
    k_scan_local<<<nbE, 1024>>>((const int*)p_cE, (int*)p_stE, (int*)p_bE, E);
    k_scan_add<<<nbE, 1024>>>((int*)p_stE, (const int*)p_bE, E);
    k_buildE<<<gpair, 256>>>(hidx, nnz);

    // ---- stream 2: convert_x first (overlaps edge CSR build), then node chain ----
    cudaStreamWaitEvent(s2, evFork, 0);
    {
        long n4 = (long)N * 32;
        k_convert_x<<<(int)((n4 + 255) / 256), 256, 0, s2>>>(x, n4);
    }
    cudaEventRecord(evX, s2);
    cudaMemsetAsync(p_cN, 0, (size_t)N * sizeof(int), s2);
    cudaMemsetAsync(p_s,  0, 32 * C * sizeof(double), s2);
    cudaMemsetAsync(p_sq, 0, 32 * C * sizeof(double), s2);
    k_countN<<<gpair, 256, 0, s2>>>(hidx, nnz);
    k_scan_local<<<nbN, 1024, 0, s2>>>((const int*)p_cN, (int*)p_stN, (int*)p_bN, N);
    k_scan_add<<<nbN, 1024, 0, s2>>>((int*)p_stN, (const int*)p_bN, N);
    k_buildN<<<gpair, 256, 0, s2>>>(hidx, nnz);
    cudaEventRecord(evJoin, s2);

    // ---- main stream: gathers + GEMM ----
    cudaStreamWaitEvent(0, evX, 0);
    k_edge_gather<<<(E + 7) / 8, 256>>>(E);
    cudaFuncSetAttribute(k_gemm, cudaFuncAttributeMaxDynamicSharedMemorySize, GEMM_SMEM_BYTES);
    k_gemm<<<(E + 63) / 64, 256, GEMM_SMEM_BYTES>>>(W, E);

    cudaStreamWaitEvent(0, evJoin, 0);
    k_node_gather<<<2048, 256>>>(hw, b, out, N);
    k_bnprep<<<1, 128>>>(gamma, beta, N);
    long n4o = (long)N * 32;
    k_bnsilu<<<(int)((n4o + 255) / 256), 256>>>(out, n4o);
}

// round 8
// speedup vs baseline: 2.3249x; 1.2250x over previous
#include <cuda_runtime.h>
#include <cuda_fp16.h>
#include <cstdint>
#include <math.h>

#define C 128
#define MAXN 100000
#define MAXE 50000
#define MAXNNZ 1600000
#define SCAN_TILE 4096
#define SAS 136   // smem row stride in halves (128 + 8 pad; keeps 16B alignment)

// ---------------- scratch (static device globals; no allocation) ----------------
__device__ __half g_xh[(size_t)MAXN * C];       // x converted to fp16
__device__ __half g_eah[(size_t)MAXE * C];      // edge features fp16 (pre-GEMM)
__device__ __half g_eahW[(size_t)MAXE * C];     // edge features after GEMM (fp16)
__device__ int    g_cntE[MAXE];
__device__ int    g_cntN[MAXN];
__device__ int    g_startE[MAXE];               // excl-scan, mutated into segment ENDs by build
__device__ int    g_startN[MAXN];
__device__ int    g_csrA[MAXNNZ];               // node ids grouped by edge
__device__ int    g_csrB[MAXNNZ];               // edge ids grouped by node
__device__ int    g_bsumE[64];
__device__ int    g_bsumN[64];
__device__ double g_sum[32 * C];                // slotted BN partials
__device__ double g_sumsq[32 * C];
__device__ float  g_scale[C];
__device__ float  g_shift[C];
__device__ int    g_is64;

// ---------------- helpers ----------------
__device__ __forceinline__ uint32_t su32(const void* p) {
    return (uint32_t)__cvta_generic_to_shared(p);
}
__device__ __forceinline__ void ldm_x4(uint32_t& r0, uint32_t& r1, uint32_t& r2, uint32_t& r3, uint32_t a) {
    asm volatile("ldmatrix.sync.aligned.m8n8.x4.shared.b16 {%0,%1,%2,%3}, [%4];"
                 : "=r"(r0), "=r"(r1), "=r"(r2), "=r"(r3) : "r"(a));
}
__device__ __forceinline__ void ldm_x4t(uint32_t& r0, uint32_t& r1, uint32_t& r2, uint32_t& r3, uint32_t a) {
    asm volatile("ldmatrix.sync.aligned.m8n8.x4.trans.shared.b16 {%0,%1,%2,%3}, [%4];"
                 : "=r"(r0), "=r"(r1), "=r"(r2), "=r"(r3) : "r"(a));
}
__device__ __forceinline__ void mma16816(float* c, uint32_t a0, uint32_t a1, uint32_t a2, uint32_t a3,
                                         uint32_t b0, uint32_t b1) {
    asm volatile("mma.sync.aligned.m16n8k16.row.col.f32.f16.f16.f32 "
                 "{%0,%1,%2,%3}, {%4,%5,%6,%7}, {%8,%9}, {%0,%1,%2,%3};"
                 : "+f"(c[0]), "+f"(c[1]), "+f"(c[2]), "+f"(c[3])
                 : "r"(a0), "r"(a1), "r"(a2), "r"(a3), "r"(b0), "r"(b1));
}

// load a pair of indices (entries 2t, 2t+1) from row starting at element offset rowoff
__device__ __forceinline__ void ldidx_pair(const void* base, long rowoff, long t,
                                           bool both, int& a, int& b) {
    if (g_is64) {
        if (both) {
            longlong2 v = ((const longlong2*)((const long long*)base + rowoff))[t];
            a = (int)v.x; b = (int)v.y;
        } else {
            a = (int)((const long long*)base)[rowoff + 2 * t];
            b = 0;
        }
    } else {
        if (both) {
            int2 v = ((const int2*)((const int*)base + rowoff))[t];
            a = v.x; b = v.y;
        } else {
            a = ((const int*)base)[rowoff + 2 * t];
            b = 0;
        }
    }
}

// accumulate 4 fp16 channels (uint2) into float4 acc
__device__ __forceinline__ void acc_half4(float4& acc, uint2 raw) {
    __half2 h0 = *(__half2*)&raw.x, h1 = *(__half2*)&raw.y;
    float2 f0 = __half22float2(h0), f1 = __half22float2(h1);
    acc.x += f0.x; acc.y += f0.y; acc.z += f1.x; acc.w += f1.y;
}

// ---------------- kernels ----------------

__global__ void k_detect(const unsigned* p) {
    if (threadIdx.x == 0) {
        int is64 = 1;
        for (int i = 0; i < 64; i++)
            if (p[2 * i + 1] != 0u) { is64 = 0; break; }
        g_is64 = is64;
    }
}

// convert x fp32 -> fp16 (4 elems per thread)
__global__ void k_convert_x(const float* __restrict__ x, long n4) {
    long i = (long)blockIdx.x * blockDim.x + threadIdx.x;
    if (i >= n4) return;
    float4 v = ((const float4*)x)[i];
    uint2 o;
    __half2 h0 = __floats2half2_rn(v.x, v.y);
    __half2 h1 = __floats2half2_rn(v.z, v.w);
    o.x = *(unsigned*)&h0; o.y = *(unsigned*)&h1;
    ((uint2*)g_xh)[i] = o;
}

// counts: 2 entries per thread via wide index loads
__global__ void k_countE(const void* __restrict__ hidx, int nnz) {
    long t = (long)blockIdx.x * blockDim.x + threadIdx.x;
    long i0 = 2 * t;
    if (i0 >= nnz) return;
    bool both = (i0 + 1 < nnz);
    int e0, e1;
    ldidx_pair(hidx, (long)nnz, t, both, e0, e1);
    atomicAdd(&g_cntE[e0], 1);
    if (both) atomicAdd(&g_cntE[e1], 1);
}
__global__ void k_countN(const void* __restrict__ hidx, int nnz) {
    long t = (long)blockIdx.x * blockDim.x + threadIdx.x;
    long i0 = 2 * t;
    if (i0 >= nnz) return;
    bool both = (i0 + 1 < nnz);
    int n0, n1;
    ldidx_pair(hidx, 0, t, both, n0, n1);
    atomicAdd(&g_cntN[n0], 1);
    if (both) atomicAdd(&g_cntN[n1], 1);
}

// pass 1: block-local exclusive scan of one 4096-elem tile + record block total
__global__ void k_scan_local(const int* __restrict__ src, int* __restrict__ dst,
                             int* __restrict__ bsum, int n) {
    __shared__ int warpsums[32];
    int tid = threadIdx.x, lane = tid & 31, wid = tid >> 5;
    int i0 = blockIdx.x * SCAN_TILE + tid * 4;

    int4 v = make_int4(0, 0, 0, 0);
    if (i0 + 3 < n) v = *(const int4*)(src + i0);
    else {
        if (i0 < n)     v.x = src[i0];
        if (i0 + 1 < n) v.y = src[i0 + 1];
        if (i0 + 2 < n) v.z = src[i0 + 2];
    }
    int t = v.x + v.y + v.z + v.w;
    int s = t;
    for (int o = 1; o < 32; o <<= 1) {
        int u = __shfl_up_sync(0xffffffffu, s, o);
        if (lane >= o) s += u;
    }
    if (lane == 31) warpsums[wid] = s;
    __syncthreads();
    if (wid == 0) {
        int ws = warpsums[lane];
        for (int o = 1; o < 32; o <<= 1) {
            int u = __shfl_up_sync(0xffffffffu, ws, o);
            if (lane >= o) ws += u;
        }
        warpsums[lane] = ws;
        if (lane == 31) bsum[blockIdx.x] = ws;
    }
    __syncthreads();
    int excl = s - t + (wid > 0 ? warpsums[wid - 1] : 0);
    int4 o4;
    o4.x = excl; o4.y = excl + v.x; o4.z = excl + v.x + v.y; o4.w = excl + v.x + v.y + v.z;
    if (i0 + 3 < n) *(int4*)(dst + i0) = o4;
    else {
        if (i0 < n)     dst[i0]     = o4.x;
        if (i0 + 1 < n) dst[i0 + 1] = o4.y;
        if (i0 + 2 < n) dst[i0 + 2] = o4.z;
    }
}

// fused pass 2+3
__global__ void k_scan_add(int* __restrict__ dst, const int* __restrict__ bsum, int n) {
    __shared__ int s_off;
    int bi = blockIdx.x;
    if (threadIdx.x == 0) {
        int run = 0;
        for (int k = 0; k < bi; k++) run += bsum[k];
        s_off = run;
    }
    __syncthreads();
    int off = s_off;
    if (off == 0) return;
    int i0 = bi * SCAN_TILE + threadIdx.x * 4;
    if (i0 + 3 < n) {
        int4 v = *(const int4*)(dst + i0);
        v.x += off; v.y += off; v.z += off; v.w += off;
        *(int4*)(dst + i0) = v;
    } else {
        if (i0 < n)     dst[i0]     += off;
        if (i0 + 1 < n) dst[i0 + 1] += off;
        if (i0 + 2 < n) dst[i0 + 2] += off;
    }
}

// Build CSR halves (2 entries/thread); atomicAdd on start doubles as cursor.
__global__ void k_buildE(const void* __restrict__ hidx, int nnz) {
    long t = (long)blockIdx.x * blockDim.x + threadIdx.x;
    long i0 = 2 * t;
    if (i0 >= nnz) return;
    bool both = (i0 + 1 < nnz);
    int n0, n1, e0, e1;
    ldidx_pair(hidx, 0, t, both, n0, n1);
    ldidx_pair(hidx, (long)nnz, t, both, e0, e1);
    int p0 = atomicAdd(&g_startE[e0], 1);
    g_csrA[p0] = n0;
    if (both) {
        int p1 = atomicAdd(&g_startE[e1], 1);
        g_csrA[p1] = n1;
    }
}
__global__ void k_buildN(const void* __restrict__ hidx, int nnz) {
    long t = (long)blockIdx.x * blockDim.x + threadIdx.x;
    long i0 = 2 * t;
    if (i0 >= nnz) return;
    bool both = (i0 + 1 < nnz);
    int n0, n1, e0, e1;
    ldidx_pair(hidx, 0, t, both, n0, n1);
    ldidx_pair(hidx, (long)nnz, t, both, e0, e1);
    int p0 = atomicAdd(&g_startN[n0], 1);
    g_csrB[p0] = e0;
    if (both) {
        int p1 = atomicAdd(&g_startN[n1], 1);
        g_csrB[p1] = e1;
    }
}

// Phase A: warp per edge; gather fp16 node rows (uint2/lane), fp32 accumulate,
// apply B^-1, write fp16.  (R5/R7-proven structure)
__global__ void k_edge_gather(int E) {
    int e = blockIdx.x * 8 + (threadIdx.x >> 5);
    if (e >= E) return;
    int lane = threadIdx.x & 31;
    int start = (e == 0) ? 0 : g_startE[e - 1];
    int end = g_startE[e];
    float4 acc = make_float4(0.f, 0.f, 0.f, 0.f);
    int i = start;
    for (; i + 32 <= end; i += 32) {
        int my = g_csrA[i + lane];
#pragma unroll 8
        for (int j = 0; j < 32; j++) {
            int nd = __shfl_sync(0xffffffffu, my, j);
            acc_half4(acc, ((const uint2*)g_xh)[(size_t)nd * 32 + lane]);
        }
    }
    int rem = end - i;
    if (rem > 0) {
        int my = (lane < rem) ? g_csrA[i + lane] : 0;
#pragma unroll 4
        for (int j = 0; j < rem; j++) {
            int nd = __shfl_sync(0xffffffffu, my, j);
            acc_half4(acc, ((const uint2*)g_xh)[(size_t)nd * 32 + lane]);
        }
    }
    float binv = (end > start) ? 1.f / (float)(end - start) : 0.f;
    __half2 h0 = __floats2half2_rn(acc.x * binv, acc.y * binv);
    __half2 h1 = __floats2half2_rn(acc.z * binv, acc.w * binv);
    uint2 o; o.x = *(unsigned*)&h0; o.y = *(unsigned*)&h1;
    ((uint2*)g_eah)[(size_t)e * 32 + lane] = o;
}

// HMMA GEMM: eahW[r][:] = eah[r][:] @ (Wh + Wl).  M-tile 128, 256 threads (8 warps),
// warp = m16 x n128.  W split into fp16 hi + fp16 residual for near-fp32 accuracy.
#define GEMM_SMEM_BYTES (3 * 128 * SAS * 2)
__global__ void k_gemm_hmma(const float* __restrict__ W, int E) {
    extern __shared__ __half sm[];
    __half* sA  = sm;                  // [128][SAS]
    __half* sBh = sm + 128 * SAS;      // [128][SAS]  W hi
    __half* sBl = sm + 2 * 128 * SAS;  // [128][SAS]  W residual
    int tid = threadIdx.x;
    int r0 = blockIdx.x * 128;

    // stage W -> (Wh, Wl): 16384 floats, 64 per thread via float4
    for (int i = tid * 4; i < 128 * 128; i += 256 * 4) {
        float4 w = *(const float4*)(W + i);
        int k = i >> 7, n = i & 127;
        __half h0 = __float2half_rn(w.x), h1 = __float2half_rn(w.y);
        __half h2 = __float2half_rn(w.z), h3 = __float2half_rn(w.w);
        sBh[k * SAS + n + 0] = h0; sBh[k * SAS + n + 1] = h1;
        sBh[k * SAS + n + 2] = h2; sBh[k * SAS + n + 3] = h3;
        sBl[k * SAS + n + 0] = __float2half_rn(w.x - __half2float(h0));
        sBl[k * SAS + n + 1] = __float2half_rn(w.y - __half2float(h1));
        sBl[k * SAS + n + 2] = __float2half_rn(w.z - __half2float(h2));
        sBl[k * SAS + n + 3] = __float2half_rn(w.w - __half2float(h3));
    }
    // stage A tile (128 rows x 128 halves), zero-padded past E
    for (int i = tid; i < 128 * 16; i += 256) {
        int r = i >> 4, seg = i & 15;
        uint4 v = make_uint4(0u, 0u, 0u, 0u);
        int row = r0 + r;
        if (row < E) v = ((const uint4*)g_eah)[(size_t)row * 16 + seg];
        *(uint4*)&sA[r * SAS + seg * 8] = v;
    }
    __syncthreads();

    int wid = tid >> 5, lane = tid & 31;
    int m_base = wid * 16;
    float acc[16][4];
#pragma unroll
    for (int t = 0; t < 16; t++)
#pragma unroll
        for (int j = 0; j < 4; j++) acc[t][j] = 0.f;

    // ldmatrix lane addressing (same row/col split for A and B)
    int l7 = lane & 7, g8 = (lane >> 3) & 1, hi = lane >> 4;
    uint32_t aBase  = su32(&sA [(m_base + l7 + g8 * 8) * SAS + hi * 8]);
    uint32_t bBaseH = su32(&sBh[(l7 + g8 * 8) * SAS + hi * 8]);
    uint32_t bBaseL = su32(&sBl[(l7 + g8 * 8) * SAS + hi * 8]);

#pragma unroll
    for (int kk = 0; kk < 8; kk++) {
        uint32_t a0, a1, a2, a3;
        ldm_x4(a0, a1, a2, a3, aBase + kk * 32);            // +16 halves in k
        uint32_t bkOff = (uint32_t)(kk * 16 * SAS * 2);     // +16 rows in k
#pragma unroll
        for (int p = 0; p < 8; p++) {
            uint32_t b0, b1, b2, b3;
            ldm_x4t(b0, b1, b2, b3, bBaseH + bkOff + p * 32);   // tiles 2p, 2p+1
            mma16816(acc[2 * p],     a0, a1, a2, a3, b0, b1);
            mma16816(acc[2 * p + 1], a0, a1, a2, a3, b2, b3);
            ldm_x4t(b0, b1, b2, b3, bBaseL + bkOff + p * 32);
            mma16816(acc[2 * p],     a0, a1, a2, a3, b0, b1);
            mma16816(acc[2 * p + 1], a0, a1, a2, a3, b2, b3);
        }
    }

    // epilogue: c-fragment layout -> fp16 global
    int grp = lane >> 2, q = lane & 3;
    int rowA = r0 + m_base + grp;
    int rowB = rowA + 8;
#pragma unroll
    for (int t = 0; t < 16; t++) {
        int col = t * 8 + q * 2;
        if (rowA < E) {
            __half2 h = __floats2half2_rn(acc[t][0], acc[t][1]);
            *(__half2*)&g_eahW[(size_t)rowA * 128 + col] = h;
        }
        if (rowB < E) {
            __half2 h = __floats2half2_rn(acc[t][2], acc[t][3]);
            *(__half2*)&g_eahW[(size_t)rowB * 128 + col] = h;
        }
    }
}

// Phase B: warp per node (grid-stride). Gather fp16 e_featW rows (uint2/lane),
// D^-1 from hw (lane-parallel + warp reduce), add bias, write fp32, BN partials.
__global__ void k_node_gather(const float* __restrict__ hw, const float* __restrict__ b,
                              float* __restrict__ out, int N) {
    int lane = threadIdx.x & 31;
    int gwarp = (int)((blockIdx.x * blockDim.x + threadIdx.x) >> 5);
    int nw = (int)((gridDim.x * blockDim.x) >> 5);
    float4 bc = ((const float4*)b)[lane];
    float4 s1 = make_float4(0.f, 0.f, 0.f, 0.f);
    float4 s2 = make_float4(0.f, 0.f, 0.f, 0.f);

    for (int v = gwarp; v < N; v += nw) {
        int start = (v == 0) ? 0 : g_startN[v - 1];
        int end = g_startN[v];
        float4 acc = make_float4(0.f, 0.f, 0.f, 0.f);
        float wlocal = 0.f;
        int i = start;
        for (; i + 32 <= end; i += 32) {
            int my = g_csrB[i + lane];
            wlocal += __ldg(&hw[my]);
#pragma unroll 8
            for (int j = 0; j < 32; j++) {
                int e = __shfl_sync(0xffffffffu, my, j);
                acc_half4(acc, ((const uint2*)g_eahW)[(size_t)e * 32 + lane]);
            }
        }
        int rem = end - i;
        if (rem > 0) {
            int my = (lane < rem) ? g_csrB[i + lane] : 0;
            if (lane < rem) wlocal += __ldg(&hw[my]);
#pragma unroll 4
            for (int j = 0; j < rem; j++) {
                int e = __shfl_sync(0xffffffffu, my, j);
                acc_half4(acc, ((const uint2*)g_eahW)[(size_t)e * 32 + lane]);
            }
        }
        float wsum = wlocal;
#pragma unroll
        for (int o = 16; o > 0; o >>= 1) wsum += __shfl_xor_sync(0xffffffffu, wsum, o);
        float dinv = wsum > 0.f ? 1.f / wsum : 0.f;
        float4 val;
        val.x = acc.x * dinv + bc.x; val.y = acc.y * dinv + bc.y;
        val.z = acc.z * dinv + bc.z; val.w = acc.w * dinv + bc.w;
        ((float4*)out)[(size_t)v * 32 + lane] = val;
        s1.x += val.x; s1.y += val.y; s1.z += val.z; s1.w += val.w;
        s2.x += val.x * val.x; s2.y += val.y * val.y;
        s2.z += val.z * val.z; s2.w += val.w * val.w;
    }

    __shared__ float sh1[128], sh2[128];
    int tid = threadIdx.x;
    if (tid < 128) { sh1[tid] = 0.f; sh2[tid] = 0.f; }
    __syncthreads();
    int c0 = lane * 4;
    atomicAdd(&sh1[c0 + 0], s1.x); atomicAdd(&sh1[c0 + 1], s1.y);
    atomicAdd(&sh1[c0 + 2], s1.z); atomicAdd(&sh1[c0 + 3], s1.w);
    atomicAdd(&sh2[c0 + 0], s2.x); atomicAdd(&sh2[c0 + 1], s2.y);
    atomicAdd(&sh2[c0 + 2], s2.z); atomicAdd(&sh2[c0 + 3], s2.w);
    __syncthreads();
    if (tid < 128) {
        int slot = blockIdx.x & 31;
        atomicAdd(&g_sum[slot * 128 + tid],   (double)sh1[tid]);
        atomicAdd(&g_sumsq[slot * 128 + tid], (double)sh2[tid]);
    }
}

__global__ void k_bnprep(const float* __restrict__ gamma, const float* __restrict__ beta, int N) {
    int c = threadIdx.x;
    double s = 0.0, q = 0.0;
    for (int k = 0; k < 32; k++) { s += g_sum[k * 128 + c]; q += g_sumsq[k * 128 + c]; }
    double mean = s / (double)N;
    double var  = q / (double)N - mean * mean;
    float rstd = rsqrtf((float)var + 1e-5f);
    float sc = rstd * gamma[c];
    g_scale[c] = sc;
    g_shift[c] = beta[c] - (float)mean * sc;
}

__global__ void k_bnsilu(float* __restrict__ out, long n4) {
    long i = (long)blockIdx.x * blockDim.x + threadIdx.x;
    if (i >= n4) return;
    int c4 = (int)(i & 31);
    float4 v = ((float4*)out)[i];
    float r[4] = {v.x, v.y, v.z, v.w};
#pragma unroll
    for (int j = 0; j < 4; j++) {
        int c = c4 * 4 + j;
        float o = r[j] * g_scale[c] + g_shift[c];
        r[j] = o * (1.f / (1.f + __expf(-o)));
    }
    ((float4*)out)[i] = make_float4(r[0], r[1], r[2], r[3]);
}

// ---------------- launcher ----------------
extern "C" void kernel_launch(void* const* d_in, const int* in_sizes, int n_in,
                              void* d_out, int out_size) {
    const float* x     = (const float*)d_in[0];
    const void*  hidx  = d_in[1];
    const float* hw    = (const float*)d_in[2];
    const float* W     = (const float*)d_in[3];
    const float* b     = (const float*)d_in[4];
    const float* gamma = (const float*)d_in[5];
    const float* beta  = (const float*)d_in[6];
    float* out = (float*)d_out;

    int N   = in_sizes[0] / C;
    int nnz = in_sizes[1] / 2;
    int E   = in_sizes[2];

    void *p_cE, *p_cN, *p_s, *p_sq, *p_stE, *p_stN, *p_bE, *p_bN;
    cudaGetSymbolAddress(&p_cE,  g_cntE);
    cudaGetSymbolAddress(&p_cN,  g_cntN);
    cudaGetSymbolAddress(&p_s,   g_sum);
    cudaGetSymbolAddress(&p_sq,  g_sumsq);
    cudaGetSymbolAddress(&p_stE, g_startE);
    cudaGetSymbolAddress(&p_stN, g_startN);
    cudaGetSymbolAddress(&p_bE,  g_bsumE);
    cudaGetSymbolAddress(&p_bN,  g_bsumN);

    // one extra stream + events — teardown-safe footprint (R4/R7 proven)
    cudaStream_t s2;
    cudaEvent_t evFork, evJoin, evX;
    cudaStreamCreateWithFlags(&s2, cudaStreamNonBlocking);
    cudaEventCreateWithFlags(&evFork, cudaEventDisableTiming);
    cudaEventCreateWithFlags(&evJoin, cudaEventDisableTiming);
    cudaEventCreateWithFlags(&evX, cudaEventDisableTiming);

    int nbE = (E + SCAN_TILE - 1) / SCAN_TILE;
    int nbN = (N + SCAN_TILE - 1) / SCAN_TILE;
    int npair = (nnz + 1) / 2;
    int gpair = (npair + 255) / 256;

    // ---- main stream head ----
    cudaMemsetAsync(p_cE, 0, (size_t)E * sizeof(int), 0);
    k_detect<<<1, 32>>>((const unsigned*)hidx);
    cudaEventRecord(evFork, 0);

    // ---- main stream: edge chain ----
    k_countE<<<gpair, 256>>>(hidx, nnz);
    k_scan_local<<<nbE, 1024>>>((const int*)p_cE, (int*)p_stE, (int*)p_bE, E);
    k_scan_add<<<nbE, 1024>>>((int*)p_stE, (const int*)p_bE, E);
    k_buildE<<<gpair, 256>>>(hidx, nnz);

    // ---- stream 2: convert_x first (overlaps edge CSR build), then node chain ----
    cudaStreamWaitEvent(s2, evFork, 0);
    {
        long n4 = (long)N * 32;
        k_convert_x<<<(int)((n4 + 255) / 256), 256, 0, s2>>>(x, n4);
    }
    cudaEventRecord(evX, s2);
    cudaMemsetAsync(p_cN, 0, (size_t)N * sizeof(int), s2);
    cudaMemsetAsync(p_s,  0, 32 * C * sizeof(double), s2);
    cudaMemsetAsync(p_sq, 0, 32 * C * sizeof(double), s2);
    k_countN<<<gpair, 256, 0, s2>>>(hidx, nnz);
    k_scan_local<<<nbN, 1024, 0, s2>>>((const int*)p_cN, (int*)p_stN, (int*)p_bN, N);
    k_scan_add<<<nbN, 1024, 0, s2>>>((int*)p_stN, (const int*)p_bN, N);
    k_buildN<<<gpair, 256, 0, s2>>>(hidx, nnz);
    cudaEventRecord(evJoin, s2);

    // ---- main stream: gathers + HMMA GEMM ----
    cudaStreamWaitEvent(0, evX, 0);
    k_edge_gather<<<(E + 7) / 8, 256>>>(E);
    cudaFuncSetAttribute(k_gemm_hmma, cudaFuncAttributeMaxDynamicSharedMemorySize, GEMM_SMEM_BYTES);
    k_gemm_hmma<<<(E + 127) / 128, 256, GEMM_SMEM_BYTES>>>(W, E);

    cudaStreamWaitEvent(0, evJoin, 0);
    k_node_gather<<<2048, 256>>>(hw, b, out, N);
    k_bnprep<<<1, 128>>>(gamma, beta, N);
    long n4o = (long)N * 32;
    k_bnsilu<<<(int)((n4o + 255) / 256), 256>>>(out, n4o);
}